// round 1
// baseline (speedup 1.0000x reference)
#include <cuda_runtime.h>
#include <math.h>

// Problem dims
#define MTOK   4096      // B*S
#define DMODEL 2048
#define NHEAD  16
#define HDIM   128
#define FFDIM  8192
#define SEQ    2048

// ---------------- scratch (device globals: allocation-free) ----------------
__device__ float g_h [MTOK * DMODEL];          // LN output (reused)
__device__ float g_q [MTOK * DMODEL];          // Q [B,S,H,HD]
__device__ float g_k [MTOK * HDIM];            // K [B,S,HD]
__device__ float g_v [MTOK * HDIM];            // V
__device__ float g_o [MTOK * DMODEL];          // attn O [B,S,H,HD]
__device__ float g_x1[MTOK * DMODEL];          // x + attn_out
__device__ float g_ff[(size_t)MTOK * FFDIM];   // FF1 output

// ---------------- helpers ----------------
__device__ __forceinline__ float gelu_exact(float x) {
    return 0.5f * x * (1.0f + erff(x * 0.70710678118654752f));
}

// ---------------- LayerNorm: one block per row ----------------
__global__ __launch_bounds__(256) void ln_kernel(
    const float* __restrict__ x, const float* __restrict__ sc,
    const float* __restrict__ bi, float* __restrict__ out)
{
    int row = blockIdx.x, tid = threadIdx.x;
    const float4* xr = (const float4*)(x + (size_t)row * DMODEL);
    float4 a = xr[tid];
    float4 b = xr[tid + 256];
    float s  = a.x + a.y + a.z + a.w + b.x + b.y + b.z + b.w;
    float ss = a.x*a.x + a.y*a.y + a.z*a.z + a.w*a.w
             + b.x*b.x + b.y*b.y + b.z*b.z + b.w*b.w;
    __shared__ float rs[8], rss[8];
    #pragma unroll
    for (int off = 16; off; off >>= 1) {
        s  += __shfl_xor_sync(0xffffffffu, s,  off);
        ss += __shfl_xor_sync(0xffffffffu, ss, off);
    }
    if ((tid & 31) == 0) { rs[tid >> 5] = s; rss[tid >> 5] = ss; }
    __syncthreads();
    float tot = 0.f, tot2 = 0.f;
    #pragma unroll
    for (int i = 0; i < 8; i++) { tot += rs[i]; tot2 += rss[i]; }
    float mean = tot * (1.0f / DMODEL);
    float var  = tot2 * (1.0f / DMODEL) - mean * mean;
    float rstd = rsqrtf(var + 1e-5f);

    const float4* s4 = (const float4*)sc;
    const float4* b4 = (const float4*)bi;
    float4* o4 = (float4*)(out + (size_t)row * DMODEL);
    float4 sc0 = s4[tid], bi0 = b4[tid], sc1 = s4[tid + 256], bi1 = b4[tid + 256];
    float4 r0, r1;
    r0.x = (a.x - mean) * rstd * sc0.x + bi0.x;
    r0.y = (a.y - mean) * rstd * sc0.y + bi0.y;
    r0.z = (a.z - mean) * rstd * sc0.z + bi0.z;
    r0.w = (a.w - mean) * rstd * sc0.w + bi0.w;
    r1.x = (b.x - mean) * rstd * sc1.x + bi1.x;
    r1.y = (b.y - mean) * rstd * sc1.y + bi1.y;
    r1.z = (b.z - mean) * rstd * sc1.z + bi1.z;
    r1.w = (b.w - mean) * rstd * sc1.w + bi1.w;
    o4[tid] = r0; o4[tid + 256] = r1;
}

// ---------------- SGEMM 128x128x16, 256 threads, 8x8/thread ----------------
// EPI: 0 = +bias, 1 = +bias+residual, 2 = +bias then exact GELU
template<int EPI>
__global__ __launch_bounds__(256, 2) void sgemm128(
    const float* __restrict__ A, const float* __restrict__ B,
    const float* __restrict__ bias, const float* __restrict__ res,
    float* __restrict__ C, int M, int N, int K)
{
    __shared__ float As[16][132];
    __shared__ float Bs[16][132];
    int tid  = threadIdx.x;
    int trow = tid >> 4, tcol = tid & 15;
    int bm = blockIdx.y * 128, bn = blockIdx.x * 128;

    float acc[8][8];
    #pragma unroll
    for (int i = 0; i < 8; i++)
        #pragma unroll
        for (int j = 0; j < 8; j++) acc[i][j] = 0.f;

    int arow = tid >> 2;             // 0..63 (+64 second half)
    int acol = (tid & 3) << 2;       // 0,4,8,12
    int brow = tid >> 5;             // 0..7  (+8 second half)
    int bcol = (tid & 31) << 2;      // 0..124

    for (int k0 = 0; k0 < K; k0 += 16) {
        #pragma unroll
        for (int it = 0; it < 2; it++) {
            int r = arow + it * 64;
            float4 av = *(const float4*)&A[(size_t)(bm + r) * K + k0 + acol];
            As[acol + 0][r] = av.x; As[acol + 1][r] = av.y;
            As[acol + 2][r] = av.z; As[acol + 3][r] = av.w;
        }
        #pragma unroll
        for (int it = 0; it < 2; it++) {
            int r = brow + it * 8;
            *(float4*)&Bs[r][bcol] = *(const float4*)&B[(size_t)(k0 + r) * N + bn + bcol];
        }
        __syncthreads();
        #pragma unroll
        for (int kk = 0; kk < 16; kk++) {
            float4 a0 = *(const float4*)&As[kk][trow * 4];
            float4 a1 = *(const float4*)&As[kk][64 + trow * 4];
            float4 b0 = *(const float4*)&Bs[kk][tcol * 4];
            float4 b1 = *(const float4*)&Bs[kk][64 + tcol * 4];
            float ra[8] = {a0.x, a0.y, a0.z, a0.w, a1.x, a1.y, a1.z, a1.w};
            float rb[8] = {b0.x, b0.y, b0.z, b0.w, b1.x, b1.y, b1.z, b1.w};
            #pragma unroll
            for (int i = 0; i < 8; i++)
                #pragma unroll
                for (int j = 0; j < 8; j++)
                    acc[i][j] = fmaf(ra[i], rb[j], acc[i][j]);
        }
        __syncthreads();
    }

    #pragma unroll
    for (int hi = 0; hi < 2; hi++) {
        #pragma unroll
        for (int i = 0; i < 4; i++) {
            int r = bm + hi * 64 + trow * 4 + i;
            #pragma unroll
            for (int hj = 0; hj < 2; hj++) {
                int c = bn + hj * 64 + tcol * 4;
                float4 bv = *(const float4*)&bias[c];
                float v0 = acc[hi*4+i][hj*4+0] + bv.x;
                float v1 = acc[hi*4+i][hj*4+1] + bv.y;
                float v2 = acc[hi*4+i][hj*4+2] + bv.z;
                float v3 = acc[hi*4+i][hj*4+3] + bv.w;
                if (EPI == 1) {
                    float4 rv = *(const float4*)&res[(size_t)r * N + c];
                    v0 += rv.x; v1 += rv.y; v2 += rv.z; v3 += rv.w;
                }
                if (EPI == 2) {
                    v0 = gelu_exact(v0); v1 = gelu_exact(v1);
                    v2 = gelu_exact(v2); v3 = gelu_exact(v3);
                }
                float4 ov = make_float4(v0, v1, v2, v3);
                *(float4*)&C[(size_t)r * N + c] = ov;
            }
        }
    }
}

// ---------------- SGEMM 64x64x16, 256 threads, 4x4/thread (narrow N) -------
template<int EPI>
__global__ __launch_bounds__(256) void sgemm64(
    const float* __restrict__ A, const float* __restrict__ B,
    const float* __restrict__ bias, const float* __restrict__ res,
    float* __restrict__ C, int M, int N, int K)
{
    __shared__ float As[16][68];
    __shared__ float Bs[16][68];
    int tid = threadIdx.x;
    int trow = tid >> 4, tcol = tid & 15;
    int bm = blockIdx.y * 64, bn = blockIdx.x * 64;

    float acc[4][4];
    #pragma unroll
    for (int i = 0; i < 4; i++)
        #pragma unroll
        for (int j = 0; j < 4; j++) acc[i][j] = 0.f;

    int arow = tid >> 2;          // 0..63
    int acol = (tid & 3) << 2;    // 0,4,8,12
    int brow = tid >> 4;          // 0..15
    int bcol = (tid & 15) << 2;   // 0..60

    for (int k0 = 0; k0 < K; k0 += 16) {
        float4 av = *(const float4*)&A[(size_t)(bm + arow) * K + k0 + acol];
        As[acol + 0][arow] = av.x; As[acol + 1][arow] = av.y;
        As[acol + 2][arow] = av.z; As[acol + 3][arow] = av.w;
        *(float4*)&Bs[brow][bcol] = *(const float4*)&B[(size_t)(k0 + brow) * N + bn + bcol];
        __syncthreads();
        #pragma unroll
        for (int kk = 0; kk < 16; kk++) {
            float4 a0 = *(const float4*)&As[kk][trow * 4];
            float4 b0 = *(const float4*)&Bs[kk][tcol * 4];
            float ra[4] = {a0.x, a0.y, a0.z, a0.w};
            float rb[4] = {b0.x, b0.y, b0.z, b0.w};
            #pragma unroll
            for (int i = 0; i < 4; i++)
                #pragma unroll
                for (int j = 0; j < 4; j++)
                    acc[i][j] = fmaf(ra[i], rb[j], acc[i][j]);
        }
        __syncthreads();
    }

    #pragma unroll
    for (int i = 0; i < 4; i++) {
        int r = bm + trow * 4 + i;
        int c = bn + tcol * 4;
        float4 bv = *(const float4*)&bias[c];
        float v0 = acc[i][0] + bv.x;
        float v1 = acc[i][1] + bv.y;
        float v2 = acc[i][2] + bv.z;
        float v3 = acc[i][3] + bv.w;
        if (EPI == 1) {
            float4 rv = *(const float4*)&res[(size_t)r * N + c];
            v0 += rv.x; v1 += rv.y; v2 += rv.z; v3 += rv.w;
        }
        *(float4*)&C[(size_t)r * N + c] = make_float4(v0, v1, v2, v3);
    }
}

// ---------------- Flash attention (fp32, causal, MQA) ----------------
// BQ=BK=64, 256 threads (16x16). Per thread: 4 q-rows; QK cols = 4 k, PV cols = 8 dims.
#define ATTN_SMEM_FLOATS (64*128 + 64*132 + 64*132 + 64*64)
#define ATTN_SMEM_BYTES  (ATTN_SMEM_FLOATS * 4)

__global__ __launch_bounds__(256) void attn_kernel(
    const float* __restrict__ q, const float* __restrict__ k,
    const float* __restrict__ v, float* __restrict__ o)
{
    extern __shared__ float sm[];
    float* Qs = sm;                    // [64][128]
    float* Ks = Qs + 64 * 128;         // [64][132]
    float* Vs = Ks + 64 * 132;         // [64][132]
    float* Ps = Vs + 64 * 132;         // [64][64]

    int tid = threadIdx.x;
    int qt  = (int)gridDim.x - 1 - (int)blockIdx.x;  // longest blocks launch first
    int bh  = blockIdx.y;
    int b   = bh >> 4, h = bh & 15;
    int qs0 = qt * 64;

    const float* kp = k + (size_t)b * SEQ * HDIM;
    const float* vp = v + (size_t)b * SEQ * HDIM;

    for (int i = tid; i < 64 * 32; i += 256) {
        int r = i >> 5, c = (i & 31) << 2;
        *(float4*)&Qs[r * 128 + c] =
            *(const float4*)&q[(((size_t)(b * SEQ + qs0 + r)) * NHEAD + h) * HDIM + c];
    }

    int tr = tid >> 4, tc = tid & 15;
    float m_i[4], l_i[4], oacc[4][8];
    #pragma unroll
    for (int i = 0; i < 4; i++) {
        m_i[i] = -1e30f; l_i[i] = 0.f;
        #pragma unroll
        for (int j = 0; j < 8; j++) oacc[i][j] = 0.f;
    }
    const float scale = 0.08838834764831845f;  // 1/sqrt(128)

    for (int kt = 0; kt <= qt; kt++) {
        int ks0 = kt * 64;
        __syncthreads();
        for (int i = tid; i < 64 * 32; i += 256) {
            int r = i >> 5, c = (i & 31) << 2;
            *(float4*)&Ks[r * 132 + c] = *(const float4*)&kp[(size_t)(ks0 + r) * HDIM + c];
            *(float4*)&Vs[r * 132 + c] = *(const float4*)&vp[(size_t)(ks0 + r) * HDIM + c];
        }
        __syncthreads();

        float s[4][4];
        #pragma unroll
        for (int i = 0; i < 4; i++)
            #pragma unroll
            for (int j = 0; j < 4; j++) s[i][j] = 0.f;

        for (int d = 0; d < 128; d += 4) {
            float4 qf[4], kf[4];
            #pragma unroll
            for (int i = 0; i < 4; i++) qf[i] = *(const float4*)&Qs[(tr * 4 + i) * 128 + d];
            #pragma unroll
            for (int j = 0; j < 4; j++) kf[j] = *(const float4*)&Ks[(tc * 4 + j) * 132 + d];
            #pragma unroll
            for (int i = 0; i < 4; i++)
                #pragma unroll
                for (int j = 0; j < 4; j++) {
                    s[i][j] = fmaf(qf[i].x, kf[j].x, s[i][j]);
                    s[i][j] = fmaf(qf[i].y, kf[j].y, s[i][j]);
                    s[i][j] = fmaf(qf[i].z, kf[j].z, s[i][j]);
                    s[i][j] = fmaf(qf[i].w, kf[j].w, s[i][j]);
                }
        }

        bool diag = (kt == qt);
        #pragma unroll
        for (int i = 0; i < 4; i++) {
            #pragma unroll
            for (int j = 0; j < 4; j++) {
                float val = s[i][j] * scale;
                if (diag && (ks0 + tc * 4 + j) > (qs0 + tr * 4 + i)) val = -1e30f;
                s[i][j] = val;
            }
        }

        #pragma unroll
        for (int i = 0; i < 4; i++) {
            float mx = fmaxf(fmaxf(s[i][0], s[i][1]), fmaxf(s[i][2], s[i][3]));
            #pragma unroll
            for (int off = 1; off < 16; off <<= 1)
                mx = fmaxf(mx, __shfl_xor_sync(0xffffffffu, mx, off));
            float mnew = fmaxf(m_i[i], mx);
            float p0 = __expf(s[i][0] - mnew);
            float p1 = __expf(s[i][1] - mnew);
            float p2 = __expf(s[i][2] - mnew);
            float p3 = __expf(s[i][3] - mnew);
            float rsum = p0 + p1 + p2 + p3;
            #pragma unroll
            for (int off = 1; off < 16; off <<= 1)
                rsum += __shfl_xor_sync(0xffffffffu, rsum, off);
            float alpha = __expf(m_i[i] - mnew);
            l_i[i] = l_i[i] * alpha + rsum;
            m_i[i] = mnew;
            #pragma unroll
            for (int j = 0; j < 8; j++) oacc[i][j] *= alpha;
            *(float4*)&Ps[(tr * 4 + i) * 64 + tc * 4] = make_float4(p0, p1, p2, p3);
        }
        __syncthreads();

        for (int kk = 0; kk < 64; kk += 4) {
            float4 pv[4];
            #pragma unroll
            for (int i = 0; i < 4; i++) pv[i] = *(const float4*)&Ps[(tr * 4 + i) * 64 + kk];
            #pragma unroll
            for (int u = 0; u < 4; u++) {
                float4 vv0 = *(const float4*)&Vs[(kk + u) * 132 + tc * 8];
                float4 vv1 = *(const float4*)&Vs[(kk + u) * 132 + tc * 8 + 4];
                #pragma unroll
                for (int i = 0; i < 4; i++) {
                    float pp = (u == 0) ? pv[i].x : (u == 1) ? pv[i].y
                             : (u == 2) ? pv[i].z : pv[i].w;
                    oacc[i][0] = fmaf(pp, vv0.x, oacc[i][0]);
                    oacc[i][1] = fmaf(pp, vv0.y, oacc[i][1]);
                    oacc[i][2] = fmaf(pp, vv0.z, oacc[i][2]);
                    oacc[i][3] = fmaf(pp, vv0.w, oacc[i][3]);
                    oacc[i][4] = fmaf(pp, vv1.x, oacc[i][4]);
                    oacc[i][5] = fmaf(pp, vv1.y, oacc[i][5]);
                    oacc[i][6] = fmaf(pp, vv1.z, oacc[i][6]);
                    oacc[i][7] = fmaf(pp, vv1.w, oacc[i][7]);
                }
            }
        }
    }

    #pragma unroll
    for (int i = 0; i < 4; i++) {
        float inv = 1.0f / l_i[i];
        size_t base = (((size_t)(b * SEQ + qs0 + tr * 4 + i)) * NHEAD + h) * HDIM + tc * 8;
        float4 o0 = make_float4(oacc[i][0]*inv, oacc[i][1]*inv, oacc[i][2]*inv, oacc[i][3]*inv);
        float4 o1 = make_float4(oacc[i][4]*inv, oacc[i][5]*inv, oacc[i][6]*inv, oacc[i][7]*inv);
        *(float4*)&o[base]     = o0;
        *(float4*)&o[base + 4] = o1;
    }
}

// ---------------- launch ----------------
extern "C" void kernel_launch(void* const* d_in, const int* in_sizes, int n_in,
                              void* d_out, int out_size)
{
    const float* x     = (const float*)d_in[0];
    const float* wq    = (const float*)d_in[2];
    const float* wq_b  = (const float*)d_in[3];
    const float* wk    = (const float*)d_in[4];
    const float* wk_b  = (const float*)d_in[5];
    const float* wv    = (const float*)d_in[6];
    const float* wv_b  = (const float*)d_in[7];
    const float* wo    = (const float*)d_in[8];
    const float* wo_b  = (const float*)d_in[9];
    const float* w1    = (const float*)d_in[10];
    const float* w1_b  = (const float*)d_in[11];
    const float* w2    = (const float*)d_in[12];
    const float* w2_b  = (const float*)d_in[13];
    const float* ln1_s = (const float*)d_in[14];
    const float* ln1_b = (const float*)d_in[15];
    const float* ln2_s = (const float*)d_in[16];
    const float* ln2_b = (const float*)d_in[17];
    float* out = (float*)d_out;

    float *h, *q, *k, *v, *o, *x1, *ff;
    cudaGetSymbolAddress((void**)&h,  g_h);
    cudaGetSymbolAddress((void**)&q,  g_q);
    cudaGetSymbolAddress((void**)&k,  g_k);
    cudaGetSymbolAddress((void**)&v,  g_v);
    cudaGetSymbolAddress((void**)&o,  g_o);
    cudaGetSymbolAddress((void**)&x1, g_x1);
    cudaGetSymbolAddress((void**)&ff, g_ff);

    cudaFuncSetAttribute(attn_kernel, cudaFuncAttributeMaxDynamicSharedMemorySize,
                         ATTN_SMEM_BYTES);

    // h = LN1(x)
    ln_kernel<<<MTOK, 256>>>(x, ln1_s, ln1_b, h);
    // Q = h @ wq + wq_b    [4096, 2048]
    sgemm128<0><<<dim3(DMODEL / 128, MTOK / 128), 256>>>(h, wq, wq_b, nullptr, q,
                                                         MTOK, DMODEL, DMODEL);
    // K, V = h @ wk/wv + b [4096, 128]
    sgemm64<0><<<dim3(HDIM / 64, MTOK / 64), 256>>>(h, wk, wk_b, nullptr, k,
                                                    MTOK, HDIM, DMODEL);
    sgemm64<0><<<dim3(HDIM / 64, MTOK / 64), 256>>>(h, wv, wv_b, nullptr, v,
                                                    MTOK, HDIM, DMODEL);
    // O = softmax(QK^T * scale + causal) V
    attn_kernel<<<dim3(SEQ / 64, 2 * NHEAD), 256, ATTN_SMEM_BYTES>>>(q, k, v, o);
    // x1 = x + O @ wo + wo_b
    sgemm128<1><<<dim3(DMODEL / 128, MTOK / 128), 256>>>(o, wo, wo_b, x, x1,
                                                         MTOK, DMODEL, DMODEL);
    // h = LN2(x1)
    ln_kernel<<<MTOK, 256>>>(x1, ln2_s, ln2_b, h);
    // ff = gelu(h @ w1 + w1_b)   [4096, 8192]
    sgemm128<2><<<dim3(FFDIM / 128, MTOK / 128), 256>>>(h, w1, w1_b, nullptr, ff,
                                                        MTOK, FFDIM, DMODEL);
    // out = x1 + ff @ w2 + w2_b
    sgemm128<1><<<dim3(DMODEL / 128, MTOK / 128), 256>>>(ff, w2, w2_b, x1, out,
                                                         MTOK, DMODEL, FFDIM);
}

// round 3
// speedup vs baseline: 1.3790x; 1.3790x over previous
#include <cuda_runtime.h>
#include <math.h>
#include <stdint.h>

// Problem dims
#define MTOK   4096      // B*S
#define DMODEL 2048
#define NHEAD  16
#define HDIM   128
#define FFDIM  8192
#define SEQ    2048

// ---------------- scratch (device globals: allocation-free) ----------------
__device__ float g_h [MTOK * DMODEL];          // LN output (tf32-rounded)
__device__ float g_q [MTOK * DMODEL];          // Q [B,S,H,HD]
__device__ float g_k [MTOK * HDIM];            // K
__device__ float g_v [MTOK * HDIM];            // V
__device__ float g_o [MTOK * DMODEL];          // attn O (tf32-rounded)
__device__ float g_x1[MTOK * DMODEL];          // x + attn_out
__device__ float g_ff[(size_t)MTOK * FFDIM];   // FF1 output (tf32-rounded)
// tf32-rounded weight copies
__device__ float g_wq[DMODEL * DMODEL];
__device__ float g_wk[DMODEL * HDIM];
__device__ float g_wv[DMODEL * HDIM];
__device__ float g_wo[DMODEL * DMODEL];
__device__ float g_w1[(size_t)DMODEL * FFDIM];
__device__ float g_w2[(size_t)FFDIM * DMODEL];

// ---------------- helpers ----------------
__device__ __forceinline__ float gelu_exact(float x) {
    return 0.5f * x * (1.0f + erff(x * 0.70710678118654752f));
}
__device__ __forceinline__ float to_tf32(float x) {
    float y;
    asm("cvt.rna.tf32.f32 %0, %1;" : "=f"(y) : "f"(x));
    return y;
}
__device__ __forceinline__ void cp_async16(void* smem, const void* gmem) {
    unsigned s = (unsigned)__cvta_generic_to_shared(smem);
    asm volatile("cp.async.cg.shared.global [%0], [%1], 16;\n" :: "r"(s), "l"(gmem));
}
#define CP_COMMIT() asm volatile("cp.async.commit_group;\n")
#define CP_WAIT(n)  asm volatile("cp.async.wait_group %0;\n" :: "n"(n))

__device__ __forceinline__ void mma_tf32(float* c, const uint32_t* a, const uint32_t* b) {
    asm volatile(
        "mma.sync.aligned.m16n8k8.row.col.f32.tf32.tf32.f32 "
        "{%0,%1,%2,%3}, {%4,%5,%6,%7}, {%8,%9}, {%0,%1,%2,%3};\n"
        : "+f"(c[0]), "+f"(c[1]), "+f"(c[2]), "+f"(c[3])
        : "r"(a[0]), "r"(a[1]), "r"(a[2]), "r"(a[3]), "r"(b[0]), "r"(b[1]));
}

// ---------------- tf32 rounding pre-pass (weights) ----------------
__global__ __launch_bounds__(256) void cvt_kernel(const float* __restrict__ in,
                                                  float* __restrict__ out, int n4) {
    int i = blockIdx.x * 256 + threadIdx.x;
    if (i < n4) {
        float4 v = ((const float4*)in)[i];
        v.x = to_tf32(v.x); v.y = to_tf32(v.y);
        v.z = to_tf32(v.z); v.w = to_tf32(v.w);
        ((float4*)out)[i] = v;
    }
}

// ---------------- LayerNorm (fused tf32 rounding on output) ----------------
__global__ __launch_bounds__(256) void ln_kernel(
    const float* __restrict__ x, const float* __restrict__ sc,
    const float* __restrict__ bi, float* __restrict__ out)
{
    int row = blockIdx.x, tid = threadIdx.x;
    const float4* xr = (const float4*)(x + (size_t)row * DMODEL);
    float4 a = xr[tid];
    float4 b = xr[tid + 256];
    float s  = a.x + a.y + a.z + a.w + b.x + b.y + b.z + b.w;
    float ss = a.x*a.x + a.y*a.y + a.z*a.z + a.w*a.w
             + b.x*b.x + b.y*b.y + b.z*b.z + b.w*b.w;
    __shared__ float rs[8], rss[8];
    #pragma unroll
    for (int off = 16; off; off >>= 1) {
        s  += __shfl_xor_sync(0xffffffffu, s,  off);
        ss += __shfl_xor_sync(0xffffffffu, ss, off);
    }
    if ((tid & 31) == 0) { rs[tid >> 5] = s; rss[tid >> 5] = ss; }
    __syncthreads();
    float tot = 0.f, tot2 = 0.f;
    #pragma unroll
    for (int i = 0; i < 8; i++) { tot += rs[i]; tot2 += rss[i]; }
    float mean = tot * (1.0f / DMODEL);
    float var  = tot2 * (1.0f / DMODEL) - mean * mean;
    float rstd = rsqrtf(var + 1e-5f);

    const float4* s4 = (const float4*)sc;
    const float4* b4 = (const float4*)bi;
    float4* o4 = (float4*)(out + (size_t)row * DMODEL);
    float4 sc0 = s4[tid], bi0 = b4[tid], sc1 = s4[tid + 256], bi1 = b4[tid + 256];
    float4 r0, r1;
    r0.x = to_tf32((a.x - mean) * rstd * sc0.x + bi0.x);
    r0.y = to_tf32((a.y - mean) * rstd * sc0.y + bi0.y);
    r0.z = to_tf32((a.z - mean) * rstd * sc0.z + bi0.z);
    r0.w = to_tf32((a.w - mean) * rstd * sc0.w + bi0.w);
    r1.x = to_tf32((b.x - mean) * rstd * sc1.x + bi1.x);
    r1.y = to_tf32((b.y - mean) * rstd * sc1.y + bi1.y);
    r1.z = to_tf32((b.z - mean) * rstd * sc1.z + bi1.z);
    r1.w = to_tf32((b.w - mean) * rstd * sc1.w + bi1.w);
    o4[tid] = r0; o4[tid + 256] = r1;
}

// ---------------- TF32 tensor-core GEMM ----------------
// BM=128 fixed, BN in {128,256}. 256 threads, 8 warps in 2 x 4 grid.
// Warp tile: 64 x (BN/4). mma m16n8k8, tf32 inputs, fp32 accumulate.
// EPI: 0 = +bias, 1 = +bias+residual, 2 = +bias -> GELU -> tf32-round
template<int BN, int EPI>
__global__ __launch_bounds__(256) void tgemm(
    const float* __restrict__ A, const float* __restrict__ B,
    const float* __restrict__ bias, const float* __restrict__ res,
    float* __restrict__ C, int M, int N, int K)
{
    constexpr int WN = BN / 4;       // 64 or 32
    constexpr int NI = WN / 8;       // 8 or 4
    constexpr int SA = 20;           // A smem stride (floats): conflict-free
    constexpr int SB = BN + 8;       // B smem stride: == 8 mod 32, conflict-free
    constexpr int ASZ = 128 * SA;    // per-stage floats
    constexpr int BSZ = 16 * SB;

    extern __shared__ float smem[];
    float* As = smem;               // [2][128][SA]
    float* Bs = smem + 2 * ASZ;     // [2][16][SB]

    int tid = threadIdx.x;
    int lane = tid & 31, w = tid >> 5;
    int wm = (w >> 2) * 64;         // 0 / 64
    int wn = (w & 3) * WN;
    int r  = lane >> 2, cl = lane & 3;

    int bm = blockIdx.y * 128, bn = blockIdx.x * BN;

    float acc[4][NI][4];
    #pragma unroll
    for (int mi = 0; mi < 4; mi++)
        #pragma unroll
        for (int ni = 0; ni < NI; ni++)
            #pragma unroll
            for (int j = 0; j < 4; j++) acc[mi][ni][j] = 0.f;

    // gmem -> smem tile loaders (16B cp.async)
    auto loadA = [&](int st, int k0) {
        float* dst = As + st * ASZ;
        #pragma unroll
        for (int i = 0; i < 2; i++) {
            int ch = tid + i * 256;          // 0..511
            int m = ch >> 2, kc = (ch & 3) << 2;
            cp_async16(&dst[m * SA + kc], &A[(size_t)(bm + m) * K + k0 + kc]);
        }
    };
    auto loadB = [&](int st, int k0) {
        float* dst = Bs + st * BSZ;
        #pragma unroll
        for (int i = 0; i < BN / 64; i++) {
            int ch = tid + i * 256;
            int kr = ch / (BN / 4), nc = (ch % (BN / 4)) << 2;
            cp_async16(&dst[kr * SB + nc], &B[(size_t)(k0 + kr) * N + bn + nc]);
        }
    };

    loadA(0, 0); loadB(0, 0); CP_COMMIT();
    int T = K >> 4;
    for (int t = 0; t < T; t++) {
        if (t + 1 < T) {
            loadA((t + 1) & 1, (t + 1) << 4);
            loadB((t + 1) & 1, (t + 1) << 4);
            CP_COMMIT();
            CP_WAIT(1);
        } else {
            CP_WAIT(0);
        }
        __syncthreads();
        const float* as = As + (t & 1) * ASZ;
        const float* bs = Bs + (t & 1) * BSZ;
        #pragma unroll
        for (int kk = 0; kk < 16; kk += 8) {
            uint32_t af[4][4];
            #pragma unroll
            for (int mi = 0; mi < 4; mi++) {
                int m0 = wm + mi * 16;
                af[mi][0] = __float_as_uint(as[(m0 + r    ) * SA + kk + cl    ]);
                af[mi][1] = __float_as_uint(as[(m0 + r + 8) * SA + kk + cl    ]);
                af[mi][2] = __float_as_uint(as[(m0 + r    ) * SA + kk + cl + 4]);
                af[mi][3] = __float_as_uint(as[(m0 + r + 8) * SA + kk + cl + 4]);
            }
            uint32_t bf[NI][2];
            #pragma unroll
            for (int ni = 0; ni < NI; ni++) {
                int n0 = wn + ni * 8;
                bf[ni][0] = __float_as_uint(bs[(kk + cl    ) * SB + n0 + r]);
                bf[ni][1] = __float_as_uint(bs[(kk + cl + 4) * SB + n0 + r]);
            }
            #pragma unroll
            for (int mi = 0; mi < 4; mi++)
                #pragma unroll
                for (int ni = 0; ni < NI; ni++)
                    mma_tf32(acc[mi][ni], af[mi], bf[ni]);
        }
        __syncthreads();
    }

    // epilogue: each thread owns pairs (row, col..col+1) and (row+8, ...)
    #pragma unroll
    for (int mi = 0; mi < 4; mi++) {
        #pragma unroll
        for (int ni = 0; ni < NI; ni++) {
            int row0 = bm + wm + mi * 16 + r;
            int col  = bn + wn + ni * 8 + cl * 2;
            float2 bv = *(const float2*)&bias[col];
            #pragma unroll
            for (int hh = 0; hh < 2; hh++) {
                int row = row0 + hh * 8;
                float v0 = acc[mi][ni][hh * 2 + 0] + bv.x;
                float v1 = acc[mi][ni][hh * 2 + 1] + bv.y;
                if (EPI == 1) {
                    float2 rv = *(const float2*)&res[(size_t)row * N + col];
                    v0 += rv.x; v1 += rv.y;
                }
                if (EPI == 2) {
                    v0 = to_tf32(gelu_exact(v0));
                    v1 = to_tf32(gelu_exact(v1));
                }
                *(float2*)&C[(size_t)row * N + col] = make_float2(v0, v1);
            }
        }
    }
}

// ---------------- Flash attention (fp32, causal, MQA) ----------------
#define ATTN_SMEM_FLOATS (64*128 + 64*132 + 64*132 + 64*64)
#define ATTN_SMEM_BYTES  (ATTN_SMEM_FLOATS * 4)

__global__ __launch_bounds__(256) void attn_kernel(
    const float* __restrict__ q, const float* __restrict__ k,
    const float* __restrict__ v, float* __restrict__ o)
{
    extern __shared__ float sm[];
    float* Qs = sm;                    // [64][128]
    float* Ks = Qs + 64 * 128;         // [64][132]
    float* Vs = Ks + 64 * 132;         // [64][132]
    float* Ps = Vs + 64 * 132;         // [64][64]

    int tid = threadIdx.x;
    int qt  = (int)gridDim.x - 1 - (int)blockIdx.x;
    int bh  = blockIdx.y;
    int b   = bh >> 4, h = bh & 15;
    int qs0 = qt * 64;

    const float* kp = k + (size_t)b * SEQ * HDIM;
    const float* vp = v + (size_t)b * SEQ * HDIM;

    for (int i = tid; i < 64 * 32; i += 256) {
        int rr = i >> 5, c = (i & 31) << 2;
        *(float4*)&Qs[rr * 128 + c] =
            *(const float4*)&q[(((size_t)(b * SEQ + qs0 + rr)) * NHEAD + h) * HDIM + c];
    }

    int tr = tid >> 4, tc = tid & 15;
    float m_i[4], l_i[4], oacc[4][8];
    #pragma unroll
    for (int i = 0; i < 4; i++) {
        m_i[i] = -1e30f; l_i[i] = 0.f;
        #pragma unroll
        for (int j = 0; j < 8; j++) oacc[i][j] = 0.f;
    }
    const float scale = 0.08838834764831845f;

    for (int kt = 0; kt <= qt; kt++) {
        int ks0 = kt * 64;
        __syncthreads();
        for (int i = tid; i < 64 * 32; i += 256) {
            int rr = i >> 5, c = (i & 31) << 2;
            *(float4*)&Ks[rr * 132 + c] = *(const float4*)&kp[(size_t)(ks0 + rr) * HDIM + c];
            *(float4*)&Vs[rr * 132 + c] = *(const float4*)&vp[(size_t)(ks0 + rr) * HDIM + c];
        }
        __syncthreads();

        float s[4][4];
        #pragma unroll
        for (int i = 0; i < 4; i++)
            #pragma unroll
            for (int j = 0; j < 4; j++) s[i][j] = 0.f;

        for (int d = 0; d < 128; d += 4) {
            float4 qf[4], kf[4];
            #pragma unroll
            for (int i = 0; i < 4; i++) qf[i] = *(const float4*)&Qs[(tr * 4 + i) * 128 + d];
            #pragma unroll
            for (int j = 0; j < 4; j++) kf[j] = *(const float4*)&Ks[(tc * 4 + j) * 132 + d];
            #pragma unroll
            for (int i = 0; i < 4; i++)
                #pragma unroll
                for (int j = 0; j < 4; j++) {
                    s[i][j] = fmaf(qf[i].x, kf[j].x, s[i][j]);
                    s[i][j] = fmaf(qf[i].y, kf[j].y, s[i][j]);
                    s[i][j] = fmaf(qf[i].z, kf[j].z, s[i][j]);
                    s[i][j] = fmaf(qf[i].w, kf[j].w, s[i][j]);
                }
        }

        bool diag = (kt == qt);
        #pragma unroll
        for (int i = 0; i < 4; i++)
            #pragma unroll
            for (int j = 0; j < 4; j++) {
                float val = s[i][j] * scale;
                if (diag && (ks0 + tc * 4 + j) > (qs0 + tr * 4 + i)) val = -1e30f;
                s[i][j] = val;
            }

        #pragma unroll
        for (int i = 0; i < 4; i++) {
            float mx = fmaxf(fmaxf(s[i][0], s[i][1]), fmaxf(s[i][2], s[i][3]));
            #pragma unroll
            for (int off = 1; off < 16; off <<= 1)
                mx = fmaxf(mx, __shfl_xor_sync(0xffffffffu, mx, off));
            float mnew = fmaxf(m_i[i], mx);
            float p0 = __expf(s[i][0] - mnew);
            float p1 = __expf(s[i][1] - mnew);
            float p2 = __expf(s[i][2] - mnew);
            float p3 = __expf(s[i][3] - mnew);
            float rsum = p0 + p1 + p2 + p3;
            #pragma unroll
            for (int off = 1; off < 16; off <<= 1)
                rsum += __shfl_xor_sync(0xffffffffu, rsum, off);
            float alpha = __expf(m_i[i] - mnew);
            l_i[i] = l_i[i] * alpha + rsum;
            m_i[i] = mnew;
            #pragma unroll
            for (int j = 0; j < 8; j++) oacc[i][j] *= alpha;
            *(float4*)&Ps[(tr * 4 + i) * 64 + tc * 4] = make_float4(p0, p1, p2, p3);
        }
        __syncthreads();

        for (int kk = 0; kk < 64; kk += 4) {
            float4 pv[4];
            #pragma unroll
            for (int i = 0; i < 4; i++) pv[i] = *(const float4*)&Ps[(tr * 4 + i) * 64 + kk];
            #pragma unroll
            for (int u = 0; u < 4; u++) {
                float4 vv0 = *(const float4*)&Vs[(kk + u) * 132 + tc * 8];
                float4 vv1 = *(const float4*)&Vs[(kk + u) * 132 + tc * 8 + 4];
                #pragma unroll
                for (int i = 0; i < 4; i++) {
                    float pp = (u == 0) ? pv[i].x : (u == 1) ? pv[i].y
                             : (u == 2) ? pv[i].z : pv[i].w;
                    oacc[i][0] = fmaf(pp, vv0.x, oacc[i][0]);
                    oacc[i][1] = fmaf(pp, vv0.y, oacc[i][1]);
                    oacc[i][2] = fmaf(pp, vv0.z, oacc[i][2]);
                    oacc[i][3] = fmaf(pp, vv0.w, oacc[i][3]);
                    oacc[i][4] = fmaf(pp, vv1.x, oacc[i][4]);
                    oacc[i][5] = fmaf(pp, vv1.y, oacc[i][5]);
                    oacc[i][6] = fmaf(pp, vv1.z, oacc[i][6]);
                    oacc[i][7] = fmaf(pp, vv1.w, oacc[i][7]);
                }
            }
        }
    }

    #pragma unroll
    for (int i = 0; i < 4; i++) {
        float inv = 1.0f / l_i[i];
        size_t base = (((size_t)(b * SEQ + qs0 + tr * 4 + i)) * NHEAD + h) * HDIM + tc * 8;
        float4 o0 = make_float4(to_tf32(oacc[i][0]*inv), to_tf32(oacc[i][1]*inv),
                                to_tf32(oacc[i][2]*inv), to_tf32(oacc[i][3]*inv));
        float4 o1 = make_float4(to_tf32(oacc[i][4]*inv), to_tf32(oacc[i][5]*inv),
                                to_tf32(oacc[i][6]*inv), to_tf32(oacc[i][7]*inv));
        *(float4*)&o[base]     = o0;
        *(float4*)&o[base + 4] = o1;
    }
}

// ---------------- launch ----------------
#define SMEM_T256 ((2*128*20 + 2*16*264) * 4)
#define SMEM_T128 ((2*128*20 + 2*16*136) * 4)

extern "C" void kernel_launch(void* const* d_in, const int* in_sizes, int n_in,
                              void* d_out, int out_size)
{
    const float* x     = (const float*)d_in[0];
    const float* wq    = (const float*)d_in[2];
    const float* wq_b  = (const float*)d_in[3];
    const float* wk    = (const float*)d_in[4];
    const float* wk_b  = (const float*)d_in[5];
    const float* wv    = (const float*)d_in[6];
    const float* wv_b  = (const float*)d_in[7];
    const float* wo    = (const float*)d_in[8];
    const float* wo_b  = (const float*)d_in[9];
    const float* w1    = (const float*)d_in[10];
    const float* w1_b  = (const float*)d_in[11];
    const float* w2    = (const float*)d_in[12];
    const float* w2_b  = (const float*)d_in[13];
    const float* ln1_s = (const float*)d_in[14];
    const float* ln1_b = (const float*)d_in[15];
    const float* ln2_s = (const float*)d_in[16];
    const float* ln2_b = (const float*)d_in[17];
    float* out = (float*)d_out;

    float *h, *q, *k, *v, *o, *x1, *ff;
    float *cwq, *cwk, *cwv, *cwo, *cw1, *cw2;
    cudaGetSymbolAddress((void**)&h,  g_h);
    cudaGetSymbolAddress((void**)&q,  g_q);
    cudaGetSymbolAddress((void**)&k,  g_k);
    cudaGetSymbolAddress((void**)&v,  g_v);
    cudaGetSymbolAddress((void**)&o,  g_o);
    cudaGetSymbolAddress((void**)&x1, g_x1);
    cudaGetSymbolAddress((void**)&ff, g_ff);
    cudaGetSymbolAddress((void**)&cwq, g_wq);
    cudaGetSymbolAddress((void**)&cwk, g_wk);
    cudaGetSymbolAddress((void**)&cwv, g_wv);
    cudaGetSymbolAddress((void**)&cwo, g_wo);
    cudaGetSymbolAddress((void**)&cw1, g_w1);
    cudaGetSymbolAddress((void**)&cw2, g_w2);

    cudaFuncSetAttribute(attn_kernel, cudaFuncAttributeMaxDynamicSharedMemorySize,
                         ATTN_SMEM_BYTES);
    cudaFuncSetAttribute(tgemm<256,0>, cudaFuncAttributeMaxDynamicSharedMemorySize, SMEM_T256);
    cudaFuncSetAttribute(tgemm<256,1>, cudaFuncAttributeMaxDynamicSharedMemorySize, SMEM_T256);
    cudaFuncSetAttribute(tgemm<256,2>, cudaFuncAttributeMaxDynamicSharedMemorySize, SMEM_T256);
    cudaFuncSetAttribute(tgemm<128,0>, cudaFuncAttributeMaxDynamicSharedMemorySize, SMEM_T128);

    // tf32-round the weights
    cvt_kernel<<<(DMODEL*DMODEL/4 + 255)/256, 256>>>(wq, cwq, DMODEL*DMODEL/4);
    cvt_kernel<<<(DMODEL*HDIM/4   + 255)/256, 256>>>(wk, cwk, DMODEL*HDIM/4);
    cvt_kernel<<<(DMODEL*HDIM/4   + 255)/256, 256>>>(wv, cwv, DMODEL*HDIM/4);
    cvt_kernel<<<(DMODEL*DMODEL/4 + 255)/256, 256>>>(wo, cwo, DMODEL*DMODEL/4);
    cvt_kernel<<<(DMODEL*FFDIM/4  + 255)/256, 256>>>(w1, cw1, DMODEL*FFDIM/4);
    cvt_kernel<<<(DMODEL*FFDIM/4  + 255)/256, 256>>>(w2, cw2, DMODEL*FFDIM/4);

    // h = LN1(x)  (tf32-rounded)
    ln_kernel<<<MTOK, 256>>>(x, ln1_s, ln1_b, h);
    // Q = h @ wq + wq_b    [4096, 2048]
    tgemm<256,0><<<dim3(DMODEL/256, MTOK/128), 256, SMEM_T256>>>(h, cwq, wq_b, nullptr, q,
                                                                 MTOK, DMODEL, DMODEL);
    // K, V [4096, 128]
    tgemm<128,0><<<dim3(1, MTOK/128), 256, SMEM_T128>>>(h, cwk, wk_b, nullptr, k,
                                                        MTOK, HDIM, DMODEL);
    tgemm<128,0><<<dim3(1, MTOK/128), 256, SMEM_T128>>>(h, cwv, wv_b, nullptr, v,
                                                        MTOK, HDIM, DMODEL);
    // attention
    attn_kernel<<<dim3(SEQ/64, 2*NHEAD), 256, ATTN_SMEM_BYTES>>>(q, k, v, o);
    // x1 = x + O @ wo + wo_b
    tgemm<256,1><<<dim3(DMODEL/256, MTOK/128), 256, SMEM_T256>>>(o, cwo, wo_b, x, x1,
                                                                 MTOK, DMODEL, DMODEL);
    // h = LN2(x1)
    ln_kernel<<<MTOK, 256>>>(x1, ln2_s, ln2_b, h);
    // ff = gelu(h @ w1 + w1_b)   [4096, 8192]
    tgemm<256,2><<<dim3(FFDIM/256, MTOK/128), 256, SMEM_T256>>>(h, cw1, w1_b, nullptr, ff,
                                                                MTOK, FFDIM, DMODEL);
    // out = x1 + ff @ w2 + w2_b
    tgemm<256,1><<<dim3(DMODEL/256, MTOK/128), 256, SMEM_T256>>>(ff, cw2, w2_b, x1, out,
                                                                 MTOK, DMODEL, FFDIM);
}

// round 5
// speedup vs baseline: 1.7608x; 1.2769x over previous
#include <cuda_runtime.h>
#include <cuda_fp16.h>
#include <math.h>
#include <stdint.h>

// Problem dims
#define MTOK   4096      // B*S
#define DMODEL 2048
#define NHEAD  16
#define HDIM   128
#define FFDIM  8192
#define SEQ    2048

// ---------------- scratch (device globals: allocation-free) ----------------
__device__ __half g_hh [MTOK * DMODEL];          // LN output (half)
__device__ float  g_q  [MTOK * DMODEL];          // Q [B,S,H,HD]
__device__ float  g_k  [MTOK * HDIM];            // K
__device__ float  g_v  [MTOK * HDIM];            // V
__device__ __half g_oh [MTOK * DMODEL];          // attn O (half)
__device__ float  g_x1 [MTOK * DMODEL];          // x + attn_out
__device__ __half g_ffh[(size_t)MTOK * FFDIM];   // FF1 output (half)
// transposed ([K,N] -> [N,K]) half weights
__device__ __half g_wq[DMODEL * DMODEL];
__device__ __half g_wk[DMODEL * HDIM];
__device__ __half g_wv[DMODEL * HDIM];
__device__ __half g_wo[DMODEL * DMODEL];
__device__ __half g_w1[(size_t)DMODEL * FFDIM];
__device__ __half g_w2[(size_t)FFDIM * DMODEL];

// ---------------- helpers ----------------
__device__ __forceinline__ float gelu_exact(float x) {
    return 0.5f * x * (1.0f + erff(x * 0.70710678118654752f));
}
__device__ __forceinline__ void cp16(uint32_t saddr, const void* g) {
    asm volatile("cp.async.cg.shared.global [%0], [%1], 16;" :: "r"(saddr), "l"(g));
}
#define CP_COMMIT() asm volatile("cp.async.commit_group;\n")
#define CP_WAIT(n)  asm volatile("cp.async.wait_group %0;\n" :: "n"(n))

__device__ __forceinline__ void mma_f16(float* c, const uint32_t* a, const uint32_t* b) {
    asm volatile(
        "mma.sync.aligned.m16n8k16.row.col.f32.f16.f16.f32 "
        "{%0,%1,%2,%3}, {%4,%5,%6,%7}, {%8,%9}, {%0,%1,%2,%3};\n"
        : "+f"(c[0]), "+f"(c[1]), "+f"(c[2]), "+f"(c[3])
        : "r"(a[0]), "r"(a[1]), "r"(a[2]), "r"(a[3]), "r"(b[0]), "r"(b[1]));
}

// ---------------- weight transpose + half cvt: [K,N] -> [N,K] ----------
__global__ __launch_bounds__(256) void transpose_cvt(
    const float* __restrict__ in, __half* __restrict__ out, int K, int N)
{
    __shared__ float t[32][33];
    int bx = blockIdx.x * 32, by = blockIdx.y * 32;
    int tx = threadIdx.x & 31, ty = threadIdx.x >> 5;
    #pragma unroll
    for (int i = 0; i < 32; i += 8)
        t[ty + i][tx] = in[(size_t)(by + ty + i) * N + bx + tx];
    __syncthreads();
    #pragma unroll
    for (int i = 0; i < 32; i += 8)
        out[(size_t)(bx + ty + i) * K + by + tx] = __float2half(t[tx][ty + i]);
}

// ---------------- LayerNorm (half output) ----------------
__global__ __launch_bounds__(256) void ln_kernel(
    const float* __restrict__ x, const float* __restrict__ sc,
    const float* __restrict__ bi, __half* __restrict__ out)
{
    int row = blockIdx.x, tid = threadIdx.x;
    const float4* xr = (const float4*)(x + (size_t)row * DMODEL);
    float4 a = xr[tid];
    float4 b = xr[tid + 256];
    float s  = a.x + a.y + a.z + a.w + b.x + b.y + b.z + b.w;
    float ss = a.x*a.x + a.y*a.y + a.z*a.z + a.w*a.w
             + b.x*b.x + b.y*b.y + b.z*b.z + b.w*b.w;
    __shared__ float rs[8], rss[8];
    #pragma unroll
    for (int off = 16; off; off >>= 1) {
        s  += __shfl_xor_sync(0xffffffffu, s,  off);
        ss += __shfl_xor_sync(0xffffffffu, ss, off);
    }
    if ((tid & 31) == 0) { rs[tid >> 5] = s; rss[tid >> 5] = ss; }
    __syncthreads();
    float tot = 0.f, tot2 = 0.f;
    #pragma unroll
    for (int i = 0; i < 8; i++) { tot += rs[i]; tot2 += rss[i]; }
    float mean = tot * (1.0f / DMODEL);
    float var  = tot2 * (1.0f / DMODEL) - mean * mean;
    float rstd = rsqrtf(var + 1e-5f);

    const float4* s4 = (const float4*)sc;
    const float4* b4 = (const float4*)bi;
    float4 sc0 = s4[tid], bi0 = b4[tid], sc1 = s4[tid + 256], bi1 = b4[tid + 256];
    __half* orow = out + (size_t)row * DMODEL;
    union { uint2 u; __half2 h[2]; } p0, p1;
    p0.h[0] = __floats2half2_rn((a.x - mean) * rstd * sc0.x + bi0.x,
                                (a.y - mean) * rstd * sc0.y + bi0.y);
    p0.h[1] = __floats2half2_rn((a.z - mean) * rstd * sc0.z + bi0.z,
                                (a.w - mean) * rstd * sc0.w + bi0.w);
    p1.h[0] = __floats2half2_rn((b.x - mean) * rstd * sc1.x + bi1.x,
                                (b.y - mean) * rstd * sc1.y + bi1.y);
    p1.h[1] = __floats2half2_rn((b.z - mean) * rstd * sc1.z + bi1.z,
                                (b.w - mean) * rstd * sc1.w + bi1.w);
    *(uint2*)&orow[tid * 4]         = p0.u;
    *(uint2*)&orow[(tid + 256) * 4] = p1.u;
}

// ---------------- FP16 tensor-core GEMM (mma.sync m16n8k16) ----------------
// BM=128, BN in {128,256}. 256 threads, 8 warps (2 x 4). Warp tile 64 x BN/4.
// A:  [M,K] half row-major
// Bt: [N,K] half row-major (K-major transposed weights)
// EPI: 0 = +bias (float out), 1 = +bias+residual (float out),
//      2 = +bias -> GELU (half out)
template<int BN, int EPI>
__global__ __launch_bounds__(256) void hgemm(
    const __half* __restrict__ A, const __half* __restrict__ Bt,
    const float* __restrict__ bias, const float* __restrict__ res,
    void* __restrict__ Cv, int M, int N, int K)
{
    constexpr int WN = BN / 4;       // 64 or 32
    constexpr int NI = WN / 8;       // 8 or 4
    constexpr int KS = 32;           // k per smem stage (halves)
    constexpr int SA = 40;           // A smem stride (halves) -> conflict-free
    constexpr int SB = 40;           // B smem stride (halves)
    constexpr int ASZ = 128 * SA;    // halves per A stage
    constexpr int BSZ = BN * SB;     // halves per B stage

    extern __shared__ __half smem[];
    __half* As = smem;                 // [2][128][SA]
    __half* Bs = smem + 2 * ASZ;       // [2][BN][SB]
    uint32_t sbase = (uint32_t)__cvta_generic_to_shared(smem);

    int tid = threadIdx.x;
    int lane = tid & 31, w = tid >> 5;
    int wm = (w >> 2) * 64;
    int wn = (w & 3) * WN;
    int r  = lane >> 2, cl = lane & 3;

    int bm = blockIdx.y * 128, bn = blockIdx.x * BN;

    float acc[4][NI][4];
    #pragma unroll
    for (int mi = 0; mi < 4; mi++)
        #pragma unroll
        for (int ni = 0; ni < NI; ni++)
            #pragma unroll
            for (int j = 0; j < 4; j++) acc[mi][ni][j] = 0.f;

    const __half* Arow = A + (size_t)bm * K;
    const __half* Brow = Bt + (size_t)bn * K;

    auto loadA = [&](int st, int k0) {
        uint32_t abase = sbase + st * ASZ * 2;
        #pragma unroll
        for (int i = 0; i < 2; i++) {
            int ch = tid + i * 256;              // 512 chunks: 128 rows x 4
            int m = ch >> 2, kc = (ch & 3) << 3; // kc in halves
            cp16(abase + (uint32_t)(m * SA + kc) * 2,
                 Arow + (size_t)m * K + k0 + kc);
        }
    };
    auto loadB = [&](int st, int k0) {
        uint32_t bbase = sbase + (2 * ASZ + st * BSZ) * 2;
        #pragma unroll
        for (int i = 0; i < BN / 64; i++) {
            int ch = tid + i * 256;              // BN*4 chunks
            int n = ch >> 2, kc = (ch & 3) << 3;
            cp16(bbase + (uint32_t)(n * SB + kc) * 2,
                 Brow + (size_t)n * K + k0 + kc);
        }
    };

    loadA(0, 0); loadB(0, 0); CP_COMMIT();
    int T = K / KS;
    for (int t = 0; t < T; t++) {
        if (t + 1 < T) {
            loadA((t + 1) & 1, (t + 1) * KS);
            loadB((t + 1) & 1, (t + 1) * KS);
            CP_COMMIT();
            CP_WAIT(1);
        } else {
            CP_WAIT(0);
        }
        __syncthreads();
        const __half* as = As + (t & 1) * ASZ;
        const __half* bs = Bs + (t & 1) * BSZ;
        #pragma unroll
        for (int kk = 0; kk < KS; kk += 16) {
            uint32_t af[4][4];
            #pragma unroll
            for (int mi = 0; mi < 4; mi++) {
                int m0 = wm + mi * 16;
                af[mi][0] = *(const uint32_t*)&as[(m0 + r    ) * SA + kk + cl * 2    ];
                af[mi][1] = *(const uint32_t*)&as[(m0 + r + 8) * SA + kk + cl * 2    ];
                af[mi][2] = *(const uint32_t*)&as[(m0 + r    ) * SA + kk + cl * 2 + 8];
                af[mi][3] = *(const uint32_t*)&as[(m0 + r + 8) * SA + kk + cl * 2 + 8];
            }
            uint32_t bf[NI][2];
            #pragma unroll
            for (int ni = 0; ni < NI; ni++) {
                int n0 = wn + ni * 8;
                bf[ni][0] = *(const uint32_t*)&bs[(n0 + r) * SB + kk + cl * 2    ];
                bf[ni][1] = *(const uint32_t*)&bs[(n0 + r) * SB + kk + cl * 2 + 8];
            }
            #pragma unroll
            for (int mi = 0; mi < 4; mi++)
                #pragma unroll
                for (int ni = 0; ni < NI; ni++)
                    mma_f16(acc[mi][ni], af[mi], bf[ni]);
        }
        __syncthreads();
    }

    // epilogue
    #pragma unroll
    for (int mi = 0; mi < 4; mi++) {
        #pragma unroll
        for (int ni = 0; ni < NI; ni++) {
            int row0 = bm + wm + mi * 16 + r;
            int col  = bn + wn + ni * 8 + cl * 2;
            float2 bv = *(const float2*)&bias[col];
            #pragma unroll
            for (int hh = 0; hh < 2; hh++) {
                int row = row0 + hh * 8;
                float v0 = acc[mi][ni][hh * 2 + 0] + bv.x;
                float v1 = acc[mi][ni][hh * 2 + 1] + bv.y;
                if (EPI == 1) {
                    float2 rv = *(const float2*)&res[(size_t)row * N + col];
                    v0 += rv.x; v1 += rv.y;
                }
                if (EPI == 2) {
                    __half* Ch = (__half*)Cv;
                    *(__half2*)&Ch[(size_t)row * N + col] =
                        __floats2half2_rn(gelu_exact(v0), gelu_exact(v1));
                } else {
                    float* Cf = (float*)Cv;
                    *(float2*)&Cf[(size_t)row * N + col] = make_float2(v0, v1);
                }
            }
        }
    }
}

// ---------------- Flash attention (fp32, causal, MQA; half output) ----------
#define ATTN_SMEM_FLOATS (64*128 + 64*132 + 64*132 + 64*64)
#define ATTN_SMEM_BYTES  (ATTN_SMEM_FLOATS * 4)

__global__ __launch_bounds__(256) void attn_kernel(
    const float* __restrict__ q, const float* __restrict__ k,
    const float* __restrict__ v, __half* __restrict__ o)
{
    extern __shared__ float sm[];
    float* Qs = sm;                    // [64][128]
    float* Ks = Qs + 64 * 128;         // [64][132]
    float* Vs = Ks + 64 * 132;         // [64][132]
    float* Ps = Vs + 64 * 132;         // [64][64]

    int tid = threadIdx.x;
    int qt  = (int)gridDim.x - 1 - (int)blockIdx.x;
    int bh  = blockIdx.y;
    int b   = bh >> 4, h = bh & 15;
    int qs0 = qt * 64;

    const float* kp = k + (size_t)b * SEQ * HDIM;
    const float* vp = v + (size_t)b * SEQ * HDIM;

    for (int i = tid; i < 64 * 32; i += 256) {
        int rr = i >> 5, c = (i & 31) << 2;
        *(float4*)&Qs[rr * 128 + c] =
            *(const float4*)&q[(((size_t)(b * SEQ + qs0 + rr)) * NHEAD + h) * HDIM + c];
    }

    int tr = tid >> 4, tc = tid & 15;
    float m_i[4], l_i[4], oacc[4][8];
    #pragma unroll
    for (int i = 0; i < 4; i++) {
        m_i[i] = -1e30f; l_i[i] = 0.f;
        #pragma unroll
        for (int j = 0; j < 8; j++) oacc[i][j] = 0.f;
    }
    const float scale = 0.08838834764831845f;

    for (int kt = 0; kt <= qt; kt++) {
        int ks0 = kt * 64;
        __syncthreads();
        for (int i = tid; i < 64 * 32; i += 256) {
            int rr = i >> 5, c = (i & 31) << 2;
            *(float4*)&Ks[rr * 132 + c] = *(const float4*)&kp[(size_t)(ks0 + rr) * HDIM + c];
            *(float4*)&Vs[rr * 132 + c] = *(const float4*)&vp[(size_t)(ks0 + rr) * HDIM + c];
        }
        __syncthreads();

        float s[4][4];
        #pragma unroll
        for (int i = 0; i < 4; i++)
            #pragma unroll
            for (int j = 0; j < 4; j++) s[i][j] = 0.f;

        for (int d = 0; d < 128; d += 4) {
            float4 qf[4], kf[4];
            #pragma unroll
            for (int i = 0; i < 4; i++) qf[i] = *(const float4*)&Qs[(tr * 4 + i) * 128 + d];
            #pragma unroll
            for (int j = 0; j < 4; j++) kf[j] = *(const float4*)&Ks[(tc * 4 + j) * 132 + d];
            #pragma unroll
            for (int i = 0; i < 4; i++)
                #pragma unroll
                for (int j = 0; j < 4; j++) {
                    s[i][j] = fmaf(qf[i].x, kf[j].x, s[i][j]);
                    s[i][j] = fmaf(qf[i].y, kf[j].y, s[i][j]);
                    s[i][j] = fmaf(qf[i].z, kf[j].z, s[i][j]);
                    s[i][j] = fmaf(qf[i].w, kf[j].w, s[i][j]);
                }
        }

        bool diag = (kt == qt);
        #pragma unroll
        for (int i = 0; i < 4; i++)
            #pragma unroll
            for (int j = 0; j < 4; j++) {
                float val = s[i][j] * scale;
                if (diag && (ks0 + tc * 4 + j) > (qs0 + tr * 4 + i)) val = -1e30f;
                s[i][j] = val;
            }

        #pragma unroll
        for (int i = 0; i < 4; i++) {
            float mx = fmaxf(fmaxf(s[i][0], s[i][1]), fmaxf(s[i][2], s[i][3]));
            #pragma unroll
            for (int off = 1; off < 16; off <<= 1)
                mx = fmaxf(mx, __shfl_xor_sync(0xffffffffu, mx, off));
            float mnew = fmaxf(m_i[i], mx);
            float p0 = __expf(s[i][0] - mnew);
            float p1 = __expf(s[i][1] - mnew);
            float p2 = __expf(s[i][2] - mnew);
            float p3 = __expf(s[i][3] - mnew);
            float rsum = p0 + p1 + p2 + p3;
            #pragma unroll
            for (int off = 1; off < 16; off <<= 1)
                rsum += __shfl_xor_sync(0xffffffffu, rsum, off);
            float alpha = __expf(m_i[i] - mnew);
            l_i[i] = l_i[i] * alpha + rsum;
            m_i[i] = mnew;
            #pragma unroll
            for (int j = 0; j < 8; j++) oacc[i][j] *= alpha;
            *(float4*)&Ps[(tr * 4 + i) * 64 + tc * 4] = make_float4(p0, p1, p2, p3);
        }
        __syncthreads();

        for (int kk = 0; kk < 64; kk += 4) {
            float4 pv[4];
            #pragma unroll
            for (int i = 0; i < 4; i++) pv[i] = *(const float4*)&Ps[(tr * 4 + i) * 64 + kk];
            #pragma unroll
            for (int u = 0; u < 4; u++) {
                float4 vv0 = *(const float4*)&Vs[(kk + u) * 132 + tc * 8];
                float4 vv1 = *(const float4*)&Vs[(kk + u) * 132 + tc * 8 + 4];
                #pragma unroll
                for (int i = 0; i < 4; i++) {
                    float pp = (u == 0) ? pv[i].x : (u == 1) ? pv[i].y
                             : (u == 2) ? pv[i].z : pv[i].w;
                    oacc[i][0] = fmaf(pp, vv0.x, oacc[i][0]);
                    oacc[i][1] = fmaf(pp, vv0.y, oacc[i][1]);
                    oacc[i][2] = fmaf(pp, vv0.z, oacc[i][2]);
                    oacc[i][3] = fmaf(pp, vv0.w, oacc[i][3]);
                    oacc[i][4] = fmaf(pp, vv1.x, oacc[i][4]);
                    oacc[i][5] = fmaf(pp, vv1.y, oacc[i][5]);
                    oacc[i][6] = fmaf(pp, vv1.z, oacc[i][6]);
                    oacc[i][7] = fmaf(pp, vv1.w, oacc[i][7]);
                }
            }
        }
    }

    #pragma unroll
    for (int i = 0; i < 4; i++) {
        float inv = 1.0f / l_i[i];
        size_t base = (((size_t)(b * SEQ + qs0 + tr * 4 + i)) * NHEAD + h) * HDIM + tc * 8;
        union { uint4 u; __half2 h[4]; } pk;
        pk.h[0] = __floats2half2_rn(oacc[i][0] * inv, oacc[i][1] * inv);
        pk.h[1] = __floats2half2_rn(oacc[i][2] * inv, oacc[i][3] * inv);
        pk.h[2] = __floats2half2_rn(oacc[i][4] * inv, oacc[i][5] * inv);
        pk.h[3] = __floats2half2_rn(oacc[i][6] * inv, oacc[i][7] * inv);
        *(uint4*)&o[base] = pk.u;
    }
}

// ---------------- launch ----------------
#define SMEM_H256 ((2 * 128 * 40 + 2 * 256 * 40) * 2)   // 61440
#define SMEM_H128 ((2 * 128 * 40 + 2 * 128 * 40) * 2)   // 40960

extern "C" void kernel_launch(void* const* d_in, const int* in_sizes, int n_in,
                              void* d_out, int out_size)
{
    const float* x     = (const float*)d_in[0];
    const float* wq    = (const float*)d_in[2];
    const float* wq_b  = (const float*)d_in[3];
    const float* wk    = (const float*)d_in[4];
    const float* wk_b  = (const float*)d_in[5];
    const float* wv    = (const float*)d_in[6];
    const float* wv_b  = (const float*)d_in[7];
    const float* wo    = (const float*)d_in[8];
    const float* wo_b  = (const float*)d_in[9];
    const float* w1    = (const float*)d_in[10];
    const float* w1_b  = (const float*)d_in[11];
    const float* w2    = (const float*)d_in[12];
    const float* w2_b  = (const float*)d_in[13];
    const float* ln1_s = (const float*)d_in[14];
    const float* ln1_b = (const float*)d_in[15];
    const float* ln2_s = (const float*)d_in[16];
    const float* ln2_b = (const float*)d_in[17];
    float* out = (float*)d_out;

    __half *hh, *oh, *ffh, *cwq, *cwk, *cwv, *cwo, *cw1, *cw2;
    float  *q, *k, *v, *x1;
    cudaGetSymbolAddress((void**)&hh,  g_hh);
    cudaGetSymbolAddress((void**)&q,   g_q);
    cudaGetSymbolAddress((void**)&k,   g_k);
    cudaGetSymbolAddress((void**)&v,   g_v);
    cudaGetSymbolAddress((void**)&oh,  g_oh);
    cudaGetSymbolAddress((void**)&x1,  g_x1);
    cudaGetSymbolAddress((void**)&ffh, g_ffh);
    cudaGetSymbolAddress((void**)&cwq, g_wq);
    cudaGetSymbolAddress((void**)&cwk, g_wk);
    cudaGetSymbolAddress((void**)&cwv, g_wv);
    cudaGetSymbolAddress((void**)&cwo, g_wo);
    cudaGetSymbolAddress((void**)&cw1, g_w1);
    cudaGetSymbolAddress((void**)&cw2, g_w2);

    cudaFuncSetAttribute(attn_kernel, cudaFuncAttributeMaxDynamicSharedMemorySize,
                         ATTN_SMEM_BYTES);
    cudaFuncSetAttribute(hgemm<256,0>, cudaFuncAttributeMaxDynamicSharedMemorySize, SMEM_H256);
    cudaFuncSetAttribute(hgemm<256,1>, cudaFuncAttributeMaxDynamicSharedMemorySize, SMEM_H256);
    cudaFuncSetAttribute(hgemm<256,2>, cudaFuncAttributeMaxDynamicSharedMemorySize, SMEM_H256);
    cudaFuncSetAttribute(hgemm<128,0>, cudaFuncAttributeMaxDynamicSharedMemorySize, SMEM_H128);

    // transpose + half-cvt the weights: [K,N] -> [N,K]
    transpose_cvt<<<dim3(DMODEL/32, DMODEL/32), 256>>>(wq, cwq, DMODEL, DMODEL);
    transpose_cvt<<<dim3(HDIM/32,   DMODEL/32), 256>>>(wk, cwk, DMODEL, HDIM);
    transpose_cvt<<<dim3(HDIM/32,   DMODEL/32), 256>>>(wv, cwv, DMODEL, HDIM);
    transpose_cvt<<<dim3(DMODEL/32, DMODEL/32), 256>>>(wo, cwo, DMODEL, DMODEL);
    transpose_cvt<<<dim3(FFDIM/32,  DMODEL/32), 256>>>(w1, cw1, DMODEL, FFDIM);
    transpose_cvt<<<dim3(DMODEL/32, FFDIM/32),  256>>>(w2, cw2, FFDIM, DMODEL);

    // h = LN1(x)  (half)
    ln_kernel<<<MTOK, 256>>>(x, ln1_s, ln1_b, hh);
    // Q = h @ wq + wq_b    [4096, 2048] float out
    hgemm<256,0><<<dim3(DMODEL/256, MTOK/128), 256, SMEM_H256>>>(
        hh, cwq, wq_b, nullptr, q, MTOK, DMODEL, DMODEL);
    // K, V [4096, 128] float out
    hgemm<128,0><<<dim3(1, MTOK/128), 256, SMEM_H128>>>(
        hh, cwk, wk_b, nullptr, k, MTOK, HDIM, DMODEL);
    hgemm<128,0><<<dim3(1, MTOK/128), 256, SMEM_H128>>>(
        hh, cwv, wv_b, nullptr, v, MTOK, HDIM, DMODEL);
    // attention (half out)
    attn_kernel<<<dim3(SEQ/64, 2*NHEAD), 256, ATTN_SMEM_BYTES>>>(q, k, v, oh);
    // x1 = x + O @ wo + wo_b  (float out)
    hgemm<256,1><<<dim3(DMODEL/256, MTOK/128), 256, SMEM_H256>>>(
        oh, cwo, wo_b, x, x1, MTOK, DMODEL, DMODEL);
    // h = LN2(x1) (half)
    ln_kernel<<<MTOK, 256>>>(x1, ln2_s, ln2_b, hh);
    // ff = gelu(h @ w1 + w1_b)   [4096, 8192] half out
    hgemm<256,2><<<dim3(FFDIM/256, MTOK/128), 256, SMEM_H256>>>(
        hh, cw1, w1_b, nullptr, ffh, MTOK, FFDIM, DMODEL);
    // out = x1 + ff @ w2 + w2_b (float out)
    hgemm<256,1><<<dim3(DMODEL/256, MTOK/128), 256, SMEM_H256>>>(
        ffh, cw2, w2_b, x1, out, MTOK, DMODEL, FFDIM);
}

// round 6
// speedup vs baseline: 5.7495x; 3.2652x over previous
#include <cuda_runtime.h>
#include <cuda_fp16.h>
#include <math.h>
#include <stdint.h>

// Problem dims
#define MTOK   4096      // B*S
#define DMODEL 2048
#define NHEAD  16
#define HDIM   128
#define FFDIM  8192
#define SEQ    2048

// ---------------- scratch (device globals: allocation-free) ----------------
__device__ __half g_hh [MTOK * DMODEL];          // LN output (half)
__device__ __half g_qh [MTOK * DMODEL];          // Q [B,S,H,HD] half (pre-scaled)
__device__ __half g_kh [MTOK * HDIM];            // K half
__device__ __half g_vh [MTOK * HDIM];            // V half
__device__ __half g_vt [2 * HDIM * SEQ];         // V transposed [B][HD][S]
__device__ __half g_oh [MTOK * DMODEL];          // attn O (half)
__device__ float  g_x1 [MTOK * DMODEL];          // x + attn_out
__device__ __half g_ffh[(size_t)MTOK * FFDIM];   // FF1 output (half)
// transposed ([K,N] -> [N,K]) half weights
__device__ __half g_wq[DMODEL * DMODEL];
__device__ __half g_wk[DMODEL * HDIM];
__device__ __half g_wv[DMODEL * HDIM];
__device__ __half g_wo[DMODEL * DMODEL];
__device__ __half g_w1[(size_t)DMODEL * FFDIM];
__device__ __half g_w2[(size_t)FFDIM * DMODEL];

// ---------------- helpers ----------------
__device__ __forceinline__ float gelu_exact(float x) {
    return 0.5f * x * (1.0f + erff(x * 0.70710678118654752f));
}
__device__ __forceinline__ void cp16(uint32_t saddr, const void* g) {
    asm volatile("cp.async.cg.shared.global [%0], [%1], 16;" :: "r"(saddr), "l"(g));
}
#define CP_COMMIT() asm volatile("cp.async.commit_group;\n")
#define CP_WAIT(n)  asm volatile("cp.async.wait_group %0;\n" :: "n"(n))

__device__ __forceinline__ void mma_f16(float* c, const uint32_t* a, const uint32_t* b) {
    asm volatile(
        "mma.sync.aligned.m16n8k16.row.col.f32.f16.f16.f32 "
        "{%0,%1,%2,%3}, {%4,%5,%6,%7}, {%8,%9}, {%0,%1,%2,%3};\n"
        : "+f"(c[0]), "+f"(c[1]), "+f"(c[2]), "+f"(c[3])
        : "r"(a[0]), "r"(a[1]), "r"(a[2]), "r"(a[3]), "r"(b[0]), "r"(b[1]));
}
__device__ __forceinline__ uint32_t packh2(float x, float y) {
    __half2 t = __floats2half2_rn(x, y);
    return *(uint32_t*)&t;
}

// ---------------- weight transpose + half cvt: [K,N] -> [N,K] ----------
__global__ __launch_bounds__(256) void transpose_cvt(
    const float* __restrict__ in, __half* __restrict__ out, int K, int N)
{
    __shared__ float t[32][33];
    int bx = blockIdx.x * 32, by = blockIdx.y * 32;
    int tx = threadIdx.x & 31, ty = threadIdx.x >> 5;
    #pragma unroll
    for (int i = 0; i < 32; i += 8)
        t[ty + i][tx] = in[(size_t)(by + ty + i) * N + bx + tx];
    __syncthreads();
    #pragma unroll
    for (int i = 0; i < 32; i += 8)
        out[(size_t)(bx + ty + i) * K + by + tx] = __float2half(t[tx][ty + i]);
}

// ---------------- V transpose (half): [B*S, HD] -> [B][HD][S] ----------
__global__ __launch_bounds__(256) void vtrans(
    const __half* __restrict__ in, __half* __restrict__ out)
{
    __shared__ __half t[32][34];
    int b = blockIdx.z;
    int d0 = blockIdx.x * 32, s0 = blockIdx.y * 32;
    int tx = threadIdx.x & 31, ty = threadIdx.x >> 5;
    #pragma unroll
    for (int i = 0; i < 32; i += 8)
        t[ty + i][tx] = in[(size_t)(b * SEQ + s0 + ty + i) * HDIM + d0 + tx];
    __syncthreads();
    #pragma unroll
    for (int i = 0; i < 32; i += 8)
        out[(size_t)(b * HDIM + d0 + ty + i) * SEQ + s0 + tx] = t[tx][ty + i];
}

// ---------------- LayerNorm (half output) ----------------
__global__ __launch_bounds__(256) void ln_kernel(
    const float* __restrict__ x, const float* __restrict__ sc,
    const float* __restrict__ bi, __half* __restrict__ out)
{
    int row = blockIdx.x, tid = threadIdx.x;
    const float4* xr = (const float4*)(x + (size_t)row * DMODEL);
    float4 a = xr[tid];
    float4 b = xr[tid + 256];
    float s  = a.x + a.y + a.z + a.w + b.x + b.y + b.z + b.w;
    float ss = a.x*a.x + a.y*a.y + a.z*a.z + a.w*a.w
             + b.x*b.x + b.y*b.y + b.z*b.z + b.w*b.w;
    __shared__ float rs[8], rss[8];
    #pragma unroll
    for (int off = 16; off; off >>= 1) {
        s  += __shfl_xor_sync(0xffffffffu, s,  off);
        ss += __shfl_xor_sync(0xffffffffu, ss, off);
    }
    if ((tid & 31) == 0) { rs[tid >> 5] = s; rss[tid >> 5] = ss; }
    __syncthreads();
    float tot = 0.f, tot2 = 0.f;
    #pragma unroll
    for (int i = 0; i < 8; i++) { tot += rs[i]; tot2 += rss[i]; }
    float mean = tot * (1.0f / DMODEL);
    float var  = tot2 * (1.0f / DMODEL) - mean * mean;
    float rstd = rsqrtf(var + 1e-5f);

    const float4* s4 = (const float4*)sc;
    const float4* b4 = (const float4*)bi;
    float4 sc0 = s4[tid], bi0 = b4[tid], sc1 = s4[tid + 256], bi1 = b4[tid + 256];
    __half* orow = out + (size_t)row * DMODEL;
    union { uint2 u; __half2 h[2]; } p0, p1;
    p0.h[0] = __floats2half2_rn((a.x - mean) * rstd * sc0.x + bi0.x,
                                (a.y - mean) * rstd * sc0.y + bi0.y);
    p0.h[1] = __floats2half2_rn((a.z - mean) * rstd * sc0.z + bi0.z,
                                (a.w - mean) * rstd * sc0.w + bi0.w);
    p1.h[0] = __floats2half2_rn((b.x - mean) * rstd * sc1.x + bi1.x,
                                (b.y - mean) * rstd * sc1.y + bi1.y);
    p1.h[1] = __floats2half2_rn((b.z - mean) * rstd * sc1.z + bi1.z,
                                (b.w - mean) * rstd * sc1.w + bi1.w);
    *(uint2*)&orow[tid * 4]         = p0.u;
    *(uint2*)&orow[(tid + 256) * 4] = p1.u;
}

// ---------------- FP16 tensor-core GEMM (mma.sync m16n8k16) ----------------
// EPI: 0 = +bias (float out), 1 = +bias+residual (float out),
//      2 = +bias -> GELU (half out), 3 = (+bias)*scale (half out)
template<int BN, int EPI>
__global__ __launch_bounds__(256) void hgemm(
    const __half* __restrict__ A, const __half* __restrict__ Bt,
    const float* __restrict__ bias, const float* __restrict__ res,
    void* __restrict__ Cv, int M, int N, int K, float scale)
{
    constexpr int WN = BN / 4;
    constexpr int NI = WN / 8;
    constexpr int KS = 32;
    constexpr int SA = 40;
    constexpr int SB = 40;
    constexpr int ASZ = 128 * SA;
    constexpr int BSZ = BN * SB;

    extern __shared__ __half smem[];
    __half* As = smem;
    __half* Bs = smem + 2 * ASZ;
    uint32_t sbase = (uint32_t)__cvta_generic_to_shared(smem);

    int tid = threadIdx.x;
    int lane = tid & 31, w = tid >> 5;
    int wm = (w >> 2) * 64;
    int wn = (w & 3) * WN;
    int r  = lane >> 2, cl = lane & 3;

    int bm = blockIdx.y * 128, bn = blockIdx.x * BN;

    float acc[4][NI][4];
    #pragma unroll
    for (int mi = 0; mi < 4; mi++)
        #pragma unroll
        for (int ni = 0; ni < NI; ni++)
            #pragma unroll
            for (int j = 0; j < 4; j++) acc[mi][ni][j] = 0.f;

    const __half* Arow = A + (size_t)bm * K;
    const __half* Brow = Bt + (size_t)bn * K;

    auto loadA = [&](int st, int k0) {
        uint32_t abase = sbase + st * ASZ * 2;
        #pragma unroll
        for (int i = 0; i < 2; i++) {
            int ch = tid + i * 256;
            int m = ch >> 2, kc = (ch & 3) << 3;
            cp16(abase + (uint32_t)(m * SA + kc) * 2,
                 Arow + (size_t)m * K + k0 + kc);
        }
    };
    auto loadB = [&](int st, int k0) {
        uint32_t bbase = sbase + (2 * ASZ + st * BSZ) * 2;
        #pragma unroll
        for (int i = 0; i < BN / 64; i++) {
            int ch = tid + i * 256;
            int n = ch >> 2, kc = (ch & 3) << 3;
            cp16(bbase + (uint32_t)(n * SB + kc) * 2,
                 Brow + (size_t)n * K + k0 + kc);
        }
    };

    loadA(0, 0); loadB(0, 0); CP_COMMIT();
    int T = K / KS;
    for (int t = 0; t < T; t++) {
        if (t + 1 < T) {
            loadA((t + 1) & 1, (t + 1) * KS);
            loadB((t + 1) & 1, (t + 1) * KS);
            CP_COMMIT();
            CP_WAIT(1);
        } else {
            CP_WAIT(0);
        }
        __syncthreads();
        const __half* as = As + (t & 1) * ASZ;
        const __half* bs = Bs + (t & 1) * BSZ;
        #pragma unroll
        for (int kk = 0; kk < KS; kk += 16) {
            uint32_t af[4][4];
            #pragma unroll
            for (int mi = 0; mi < 4; mi++) {
                int m0 = wm + mi * 16;
                af[mi][0] = *(const uint32_t*)&as[(m0 + r    ) * SA + kk + cl * 2    ];
                af[mi][1] = *(const uint32_t*)&as[(m0 + r + 8) * SA + kk + cl * 2    ];
                af[mi][2] = *(const uint32_t*)&as[(m0 + r    ) * SA + kk + cl * 2 + 8];
                af[mi][3] = *(const uint32_t*)&as[(m0 + r + 8) * SA + kk + cl * 2 + 8];
            }
            uint32_t bf[NI][2];
            #pragma unroll
            for (int ni = 0; ni < NI; ni++) {
                int n0 = wn + ni * 8;
                bf[ni][0] = *(const uint32_t*)&bs[(n0 + r) * SB + kk + cl * 2    ];
                bf[ni][1] = *(const uint32_t*)&bs[(n0 + r) * SB + kk + cl * 2 + 8];
            }
            #pragma unroll
            for (int mi = 0; mi < 4; mi++)
                #pragma unroll
                for (int ni = 0; ni < NI; ni++)
                    mma_f16(acc[mi][ni], af[mi], bf[ni]);
        }
        __syncthreads();
    }

    #pragma unroll
    for (int mi = 0; mi < 4; mi++) {
        #pragma unroll
        for (int ni = 0; ni < NI; ni++) {
            int row0 = bm + wm + mi * 16 + r;
            int col  = bn + wn + ni * 8 + cl * 2;
            float2 bv = *(const float2*)&bias[col];
            #pragma unroll
            for (int hh = 0; hh < 2; hh++) {
                int row = row0 + hh * 8;
                float v0 = acc[mi][ni][hh * 2 + 0] + bv.x;
                float v1 = acc[mi][ni][hh * 2 + 1] + bv.y;
                if (EPI == 1) {
                    float2 rv = *(const float2*)&res[(size_t)row * N + col];
                    v0 += rv.x; v1 += rv.y;
                }
                if (EPI == 2) {
                    __half* Ch = (__half*)Cv;
                    *(__half2*)&Ch[(size_t)row * N + col] =
                        __floats2half2_rn(gelu_exact(v0), gelu_exact(v1));
                } else if (EPI == 3) {
                    __half* Ch = (__half*)Cv;
                    *(__half2*)&Ch[(size_t)row * N + col] =
                        __floats2half2_rn(v0 * scale, v1 * scale);
                } else {
                    float* Cf = (float*)Cv;
                    *(float2*)&Cf[(size_t)row * N + col] = make_float2(v0, v1);
                }
            }
        }
    }
}

// ---------------- FP16 tensor-core flash attention ----------------
// BQ=128, BK=64, 256 threads / 8 warps, each warp owns 16 q-rows.
// Q pre-scaled by 1/sqrt(HD). K tile [64,128] native; V pre-transposed [HD][S].
#define SQ  136
#define SVT 72
#define FA_SMEM ((128*SQ + 2*64*SQ + 2*128*SVT) * 2)

__global__ __launch_bounds__(256) void fattn(
    const __half* __restrict__ q, const __half* __restrict__ k,
    const __half* __restrict__ vt, __half* __restrict__ o)
{
    extern __shared__ __half sm2[];
    __half* Qs = sm2;                    // [128][SQ]
    __half* Ks = Qs + 128 * SQ;          // [2][64][SQ]
    __half* Vs = Ks + 2 * 64 * SQ;       // [2][128][SVT]
    uint32_t qb  = (uint32_t)__cvta_generic_to_shared(Qs);
    uint32_t kbb = (uint32_t)__cvta_generic_to_shared(Ks);
    uint32_t vbb = (uint32_t)__cvta_generic_to_shared(Vs);

    int tid = threadIdx.x, lane = tid & 31, w = tid >> 5;
    int qt = (int)gridDim.x - 1 - (int)blockIdx.x;   // longest first
    int bh = blockIdx.y, b = bh >> 4, h = bh & 15;
    int qs0 = qt * 128;
    int r = lane >> 2, cl = lane & 3;
    int m0 = w * 16;

    // Q load (whole tile): 128 rows x 256B
    const __half* qp = q + ((size_t)(b * SEQ + qs0) * NHEAD + h) * HDIM;
    #pragma unroll
    for (int i = 0; i < 8; i++) {
        int ch = tid + i * 256; int rr = ch >> 4, c = (ch & 15) * 8;
        cp16(qb + (uint32_t)(rr * SQ + c) * 2, qp + (size_t)rr * (NHEAD * HDIM) + c);
    }

    auto loadKV = [&](int st, int kt) {
        int ks0 = kt * 64;
        const __half* kp = k + ((size_t)b * SEQ + ks0) * HDIM;
        uint32_t kbs = kbb + (uint32_t)st * 64 * SQ * 2;
        #pragma unroll
        for (int i = 0; i < 4; i++) {
            int ch = tid + i * 256; int rr = ch >> 4, c = (ch & 15) * 8;
            cp16(kbs + (uint32_t)(rr * SQ + c) * 2, kp + (size_t)rr * HDIM + c);
        }
        const __half* vp = vt + (size_t)b * HDIM * SEQ + ks0;
        uint32_t vbs = vbb + (uint32_t)st * 128 * SVT * 2;
        #pragma unroll
        for (int i = 0; i < 4; i++) {
            int ch = tid + i * 256; int rr = ch >> 3, c = (ch & 7) * 8;
            cp16(vbs + (uint32_t)(rr * SVT + c) * 2, vp + (size_t)rr * SEQ + c);
        }
    };

    loadKV(0, 0);
    CP_COMMIT();

    float m_0 = -1e30f, m_1 = -1e30f, l_0 = 0.f, l_1 = 0.f;
    float oacc[16][4];
    #pragma unroll
    for (int di = 0; di < 16; di++)
        #pragma unroll
        for (int j = 0; j < 4; j++) oacc[di][j] = 0.f;

    int nkt = 2 * (qt + 1);
    for (int kt = 0; kt < nkt; kt++) {
        CP_WAIT(0);
        __syncthreads();
        if (kt + 1 < nkt) { loadKV((kt + 1) & 1, kt + 1); CP_COMMIT(); }
        const __half* ks = Ks + (kt & 1) * 64 * SQ;
        const __half* vs = Vs + (kt & 1) * 128 * SVT;

        // S = Q K^T  (16 x 64 per warp)
        float sacc[8][4];
        #pragma unroll
        for (int ni = 0; ni < 8; ni++)
            #pragma unroll
            for (int j = 0; j < 4; j++) sacc[ni][j] = 0.f;

        #pragma unroll
        for (int kk = 0; kk < 128; kk += 16) {
            uint32_t af[4];
            af[0] = *(const uint32_t*)&Qs[(m0 + r    ) * SQ + kk + cl * 2    ];
            af[1] = *(const uint32_t*)&Qs[(m0 + r + 8) * SQ + kk + cl * 2    ];
            af[2] = *(const uint32_t*)&Qs[(m0 + r    ) * SQ + kk + cl * 2 + 8];
            af[3] = *(const uint32_t*)&Qs[(m0 + r + 8) * SQ + kk + cl * 2 + 8];
            #pragma unroll
            for (int ni = 0; ni < 8; ni++) {
                uint32_t bf[2];
                bf[0] = *(const uint32_t*)&ks[(ni * 8 + r) * SQ + kk + cl * 2    ];
                bf[1] = *(const uint32_t*)&ks[(ni * 8 + r) * SQ + kk + cl * 2 + 8];
                mma_f16(sacc[ni], af, bf);
            }
        }

        // causal mask (diagonal region only)
        int ks0 = kt * 64;
        if (ks0 + 63 > qs0 + m0) {
            int row0 = qs0 + m0 + r, row1 = row0 + 8;
            #pragma unroll
            for (int ni = 0; ni < 8; ni++) {
                int c0 = ks0 + ni * 8 + cl * 2, c1 = c0 + 1;
                if (c0 > row0) sacc[ni][0] = -1e30f;
                if (c1 > row0) sacc[ni][1] = -1e30f;
                if (c0 > row1) sacc[ni][2] = -1e30f;
                if (c1 > row1) sacc[ni][3] = -1e30f;
            }
        }

        // online softmax
        float mx0 = -1e30f, mx1 = -1e30f;
        #pragma unroll
        for (int ni = 0; ni < 8; ni++) {
            mx0 = fmaxf(mx0, fmaxf(sacc[ni][0], sacc[ni][1]));
            mx1 = fmaxf(mx1, fmaxf(sacc[ni][2], sacc[ni][3]));
        }
        mx0 = fmaxf(mx0, __shfl_xor_sync(0xffffffffu, mx0, 1));
        mx0 = fmaxf(mx0, __shfl_xor_sync(0xffffffffu, mx0, 2));
        mx1 = fmaxf(mx1, __shfl_xor_sync(0xffffffffu, mx1, 1));
        mx1 = fmaxf(mx1, __shfl_xor_sync(0xffffffffu, mx1, 2));
        float mn0 = fmaxf(m_0, mx0), mn1 = fmaxf(m_1, mx1);
        float a0 = __expf(m_0 - mn0), a1 = __expf(m_1 - mn1);
        float s0 = 0.f, s1 = 0.f;
        #pragma unroll
        for (int ni = 0; ni < 8; ni++) {
            sacc[ni][0] = __expf(sacc[ni][0] - mn0);
            sacc[ni][1] = __expf(sacc[ni][1] - mn0);
            sacc[ni][2] = __expf(sacc[ni][2] - mn1);
            sacc[ni][3] = __expf(sacc[ni][3] - mn1);
            s0 += sacc[ni][0] + sacc[ni][1];
            s1 += sacc[ni][2] + sacc[ni][3];
        }
        s0 += __shfl_xor_sync(0xffffffffu, s0, 1);
        s0 += __shfl_xor_sync(0xffffffffu, s0, 2);
        s1 += __shfl_xor_sync(0xffffffffu, s1, 1);
        s1 += __shfl_xor_sync(0xffffffffu, s1, 2);
        l_0 = l_0 * a0 + s0; l_1 = l_1 * a1 + s1;
        m_0 = mn0; m_1 = mn1;
        #pragma unroll
        for (int di = 0; di < 16; di++) {
            oacc[di][0] *= a0; oacc[di][1] *= a0;
            oacc[di][2] *= a1; oacc[di][3] *= a1;
        }

        // P fragments (registers -> A-frag, no smem)
        uint32_t pa[4][4];
        #pragma unroll
        for (int j = 0; j < 4; j++) {
            pa[j][0] = packh2(sacc[2*j  ][0], sacc[2*j  ][1]);
            pa[j][1] = packh2(sacc[2*j  ][2], sacc[2*j  ][3]);
            pa[j][2] = packh2(sacc[2*j+1][0], sacc[2*j+1][1]);
            pa[j][3] = packh2(sacc[2*j+1][2], sacc[2*j+1][3]);
        }

        // O += P V   (16 x 128 per warp)
        #pragma unroll
        for (int j = 0; j < 4; j++) {
            #pragma unroll
            for (int di = 0; di < 16; di++) {
                uint32_t bf[2];
                bf[0] = *(const uint32_t*)&vs[(di * 8 + r) * SVT + j * 16 + cl * 2    ];
                bf[1] = *(const uint32_t*)&vs[(di * 8 + r) * SVT + j * 16 + cl * 2 + 8];
                mma_f16(oacc[di], pa[j], bf);
            }
        }
    }

    // epilogue
    float i0 = 1.f / l_0, i1 = 1.f / l_1;
    __half* op = o + ((size_t)(b * SEQ + qs0 + m0) * NHEAD + h) * HDIM;
    #pragma unroll
    for (int di = 0; di < 16; di++) {
        int c = di * 8 + cl * 2;
        *(__half2*)&op[(size_t)r * (NHEAD * HDIM) + c] =
            __floats2half2_rn(oacc[di][0] * i0, oacc[di][1] * i0);
        *(__half2*)&op[(size_t)(r + 8) * (NHEAD * HDIM) + c] =
            __floats2half2_rn(oacc[di][2] * i1, oacc[di][3] * i1);
    }
}

// ---------------- launch ----------------
#define SMEM_H256 ((2 * 128 * 40 + 2 * 256 * 40) * 2)   // 61440
#define SMEM_H128 ((2 * 128 * 40 + 2 * 128 * 40) * 2)   // 40960

extern "C" void kernel_launch(void* const* d_in, const int* in_sizes, int n_in,
                              void* d_out, int out_size)
{
    const float* x     = (const float*)d_in[0];
    const float* wq    = (const float*)d_in[2];
    const float* wq_b  = (const float*)d_in[3];
    const float* wk    = (const float*)d_in[4];
    const float* wk_b  = (const float*)d_in[5];
    const float* wv    = (const float*)d_in[6];
    const float* wv_b  = (const float*)d_in[7];
    const float* wo    = (const float*)d_in[8];
    const float* wo_b  = (const float*)d_in[9];
    const float* w1    = (const float*)d_in[10];
    const float* w1_b  = (const float*)d_in[11];
    const float* w2    = (const float*)d_in[12];
    const float* w2_b  = (const float*)d_in[13];
    const float* ln1_s = (const float*)d_in[14];
    const float* ln1_b = (const float*)d_in[15];
    const float* ln2_s = (const float*)d_in[16];
    const float* ln2_b = (const float*)d_in[17];
    float* out = (float*)d_out;

    __half *hh, *qh, *kh, *vh, *vtp, *oh, *ffh;
    __half *cwq, *cwk, *cwv, *cwo, *cw1, *cw2;
    float  *x1;
    cudaGetSymbolAddress((void**)&hh,  g_hh);
    cudaGetSymbolAddress((void**)&qh,  g_qh);
    cudaGetSymbolAddress((void**)&kh,  g_kh);
    cudaGetSymbolAddress((void**)&vh,  g_vh);
    cudaGetSymbolAddress((void**)&vtp, g_vt);
    cudaGetSymbolAddress((void**)&oh,  g_oh);
    cudaGetSymbolAddress((void**)&x1,  g_x1);
    cudaGetSymbolAddress((void**)&ffh, g_ffh);
    cudaGetSymbolAddress((void**)&cwq, g_wq);
    cudaGetSymbolAddress((void**)&cwk, g_wk);
    cudaGetSymbolAddress((void**)&cwv, g_wv);
    cudaGetSymbolAddress((void**)&cwo, g_wo);
    cudaGetSymbolAddress((void**)&cw1, g_w1);
    cudaGetSymbolAddress((void**)&cw2, g_w2);

    cudaFuncSetAttribute(fattn, cudaFuncAttributeMaxDynamicSharedMemorySize, FA_SMEM);
    cudaFuncSetAttribute(hgemm<256,1>, cudaFuncAttributeMaxDynamicSharedMemorySize, SMEM_H256);
    cudaFuncSetAttribute(hgemm<256,2>, cudaFuncAttributeMaxDynamicSharedMemorySize, SMEM_H256);
    cudaFuncSetAttribute(hgemm<256,3>, cudaFuncAttributeMaxDynamicSharedMemorySize, SMEM_H256);
    cudaFuncSetAttribute(hgemm<128,3>, cudaFuncAttributeMaxDynamicSharedMemorySize, SMEM_H128);

    // transpose + half-cvt the weights: [K,N] -> [N,K]
    transpose_cvt<<<dim3(DMODEL/32, DMODEL/32), 256>>>(wq, cwq, DMODEL, DMODEL);
    transpose_cvt<<<dim3(HDIM/32,   DMODEL/32), 256>>>(wk, cwk, DMODEL, HDIM);
    transpose_cvt<<<dim3(HDIM/32,   DMODEL/32), 256>>>(wv, cwv, DMODEL, HDIM);
    transpose_cvt<<<dim3(DMODEL/32, DMODEL/32), 256>>>(wo, cwo, DMODEL, DMODEL);
    transpose_cvt<<<dim3(FFDIM/32,  DMODEL/32), 256>>>(w1, cw1, DMODEL, FFDIM);
    transpose_cvt<<<dim3(DMODEL/32, FFDIM/32),  256>>>(w2, cw2, FFDIM, DMODEL);

    const float qscale = 0.08838834764831845f;  // 1/sqrt(128)

    // h = LN1(x)  (half)
    ln_kernel<<<MTOK, 256>>>(x, ln1_s, ln1_b, hh);
    // Q = (h @ wq + wq_b) * qscale   (half out, pre-scaled)
    hgemm<256,3><<<dim3(DMODEL/256, MTOK/128), 256, SMEM_H256>>>(
        hh, cwq, wq_b, nullptr, qh, MTOK, DMODEL, DMODEL, qscale);
    // K, V (half out)
    hgemm<128,3><<<dim3(1, MTOK/128), 256, SMEM_H128>>>(
        hh, cwk, wk_b, nullptr, kh, MTOK, HDIM, DMODEL, 1.0f);
    hgemm<128,3><<<dim3(1, MTOK/128), 256, SMEM_H128>>>(
        hh, cwv, wv_b, nullptr, vh, MTOK, HDIM, DMODEL, 1.0f);
    // V transpose: [B*S, HD] -> [B][HD][S]
    vtrans<<<dim3(HDIM/32, SEQ/32, 2), 256>>>(vh, vtp);
    // attention (half out)
    fattn<<<dim3(SEQ/128, 2*NHEAD), 256, FA_SMEM>>>(qh, kh, vtp, oh);
    // x1 = x + O @ wo + wo_b  (float out)
    hgemm<256,1><<<dim3(DMODEL/256, MTOK/128), 256, SMEM_H256>>>(
        oh, cwo, wo_b, x, x1, MTOK, DMODEL, DMODEL, 1.0f);
    // h = LN2(x1) (half)
    ln_kernel<<<MTOK, 256>>>(x1, ln2_s, ln2_b, hh);
    // ff = gelu(h @ w1 + w1_b)  (half out)
    hgemm<256,2><<<dim3(FFDIM/256, MTOK/128), 256, SMEM_H256>>>(
        hh, cw1, w1_b, nullptr, ffh, MTOK, FFDIM, DMODEL, 1.0f);
    // out = x1 + ff @ w2 + w2_b (float out)
    hgemm<256,1><<<dim3(DMODEL/256, MTOK/128), 256, SMEM_H256>>>(
        ffh, cw2, w2_b, x1, out, MTOK, DMODEL, FFDIM, 1.0f);
}

// round 7
// speedup vs baseline: 6.1637x; 1.0720x over previous
#include <cuda_runtime.h>
#include <cuda_fp16.h>
#include <math.h>
#include <stdint.h>

// Problem dims
#define MTOK   4096      // B*S
#define DMODEL 2048
#define NHEAD  16
#define HDIM   128
#define FFDIM  8192
#define SEQ    2048
#define NQKV   2304      // 2048 + 128 + 128

// ---------------- scratch (device globals: allocation-free) ----------------
__device__ __half g_hh [MTOK * DMODEL];          // LN output (half)
__device__ __half g_qh [MTOK * DMODEL];          // Q half (pre-scaled)
__device__ __half g_kh [MTOK * HDIM];            // K half
__device__ __half g_vh [MTOK * HDIM];            // V half
__device__ __half g_vt [2 * HDIM * SEQ];         // V transposed [B][HD][S]
__device__ __half g_oh [MTOK * DMODEL];          // attn O (half)
__device__ float  g_x1 [MTOK * DMODEL];          // x + attn_out
__device__ __half g_ffh[(size_t)MTOK * FFDIM];   // FF1 output (half)
// transposed ([K,N] -> [N,K]) half weights
__device__ __half g_wqkv[(size_t)NQKV * DMODEL]; // [Q;K;V] rows
__device__ float  g_bqkv[NQKV];
__device__ __half g_wo[DMODEL * DMODEL];
__device__ __half g_w1[(size_t)DMODEL * FFDIM];
__device__ __half g_w2[(size_t)FFDIM * DMODEL];

// ---------------- helpers ----------------
__device__ __forceinline__ float gelu_exact(float x) {
    return 0.5f * x * (1.0f + erff(x * 0.70710678118654752f));
}
__device__ __forceinline__ void cp16(uint32_t saddr, const void* g) {
    asm volatile("cp.async.cg.shared.global [%0], [%1], 16;" :: "r"(saddr), "l"(g));
}
#define CP_COMMIT() asm volatile("cp.async.commit_group;\n")
#define CP_WAIT(n)  asm volatile("cp.async.wait_group %0;\n" :: "n"(n))

__device__ __forceinline__ void mma_f16(float* c, const uint32_t* a, const uint32_t* b) {
    asm volatile(
        "mma.sync.aligned.m16n8k16.row.col.f32.f16.f16.f32 "
        "{%0,%1,%2,%3}, {%4,%5,%6,%7}, {%8,%9}, {%0,%1,%2,%3};\n"
        : "+f"(c[0]), "+f"(c[1]), "+f"(c[2]), "+f"(c[3])
        : "r"(a[0]), "r"(a[1]), "r"(a[2]), "r"(a[3]), "r"(b[0]), "r"(b[1]));
}
#define LDSM4(r0, r1, r2, r3, addr) \
    asm volatile("ldmatrix.sync.aligned.m8n8.x4.shared.b16 {%0,%1,%2,%3}, [%4];" \
        : "=r"(r0), "=r"(r1), "=r"(r2), "=r"(r3) : "r"(addr))

__device__ __forceinline__ uint32_t packh2(float x, float y) {
    __half2 t = __floats2half2_rn(x, y);
    return *(uint32_t*)&t;
}

// ---------------- weight transpose + half cvt: [K,N] -> [N,K] ----------
__global__ __launch_bounds__(256) void transpose_cvt(
    const float* __restrict__ in, __half* __restrict__ out, int K, int N)
{
    __shared__ float t[32][33];
    int bx = blockIdx.x * 32, by = blockIdx.y * 32;
    int tx = threadIdx.x & 31, ty = threadIdx.x >> 5;
    #pragma unroll
    for (int i = 0; i < 32; i += 8)
        t[ty + i][tx] = in[(size_t)(by + ty + i) * N + bx + tx];
    __syncthreads();
    #pragma unroll
    for (int i = 0; i < 32; i += 8)
        out[(size_t)(bx + ty + i) * K + by + tx] = __float2half(t[tx][ty + i]);
}

__global__ void fill_bqkv(const float* __restrict__ qb, const float* __restrict__ kb,
                          const float* __restrict__ vb, float* __restrict__ o)
{
    int i = blockIdx.x * 256 + threadIdx.x;
    if (i < DMODEL) o[i] = qb[i];
    else if (i < DMODEL + HDIM) o[i] = kb[i - DMODEL];
    else if (i < NQKV) o[i] = vb[i - DMODEL - HDIM];
}

// ---------------- V transpose (half): [B*S, HD] -> [B][HD][S] ----------
__global__ __launch_bounds__(256) void vtrans(
    const __half* __restrict__ in, __half* __restrict__ out)
{
    __shared__ __half t[32][34];
    int b = blockIdx.z;
    int d0 = blockIdx.x * 32, s0 = blockIdx.y * 32;
    int tx = threadIdx.x & 31, ty = threadIdx.x >> 5;
    #pragma unroll
    for (int i = 0; i < 32; i += 8)
        t[ty + i][tx] = in[(size_t)(b * SEQ + s0 + ty + i) * HDIM + d0 + tx];
    __syncthreads();
    #pragma unroll
    for (int i = 0; i < 32; i += 8)
        out[(size_t)(b * HDIM + d0 + ty + i) * SEQ + s0 + tx] = t[tx][ty + i];
}

// ---------------- LayerNorm (half output) ----------------
__global__ __launch_bounds__(256) void ln_kernel(
    const float* __restrict__ x, const float* __restrict__ sc,
    const float* __restrict__ bi, __half* __restrict__ out)
{
    int row = blockIdx.x, tid = threadIdx.x;
    const float4* xr = (const float4*)(x + (size_t)row * DMODEL);
    float4 a = xr[tid];
    float4 b = xr[tid + 256];
    float s  = a.x + a.y + a.z + a.w + b.x + b.y + b.z + b.w;
    float ss = a.x*a.x + a.y*a.y + a.z*a.z + a.w*a.w
             + b.x*b.x + b.y*b.y + b.z*b.z + b.w*b.w;
    __shared__ float rs[8], rss[8];
    #pragma unroll
    for (int off = 16; off; off >>= 1) {
        s  += __shfl_xor_sync(0xffffffffu, s,  off);
        ss += __shfl_xor_sync(0xffffffffu, ss, off);
    }
    if ((tid & 31) == 0) { rs[tid >> 5] = s; rss[tid >> 5] = ss; }
    __syncthreads();
    float tot = 0.f, tot2 = 0.f;
    #pragma unroll
    for (int i = 0; i < 8; i++) { tot += rs[i]; tot2 += rss[i]; }
    float mean = tot * (1.0f / DMODEL);
    float var  = tot2 * (1.0f / DMODEL) - mean * mean;
    float rstd = rsqrtf(var + 1e-5f);

    const float4* s4 = (const float4*)sc;
    const float4* b4 = (const float4*)bi;
    float4 sc0 = s4[tid], bi0 = b4[tid], sc1 = s4[tid + 256], bi1 = b4[tid + 256];
    __half* orow = out + (size_t)row * DMODEL;
    union { uint2 u; __half2 h[2]; } p0, p1;
    p0.h[0] = __floats2half2_rn((a.x - mean) * rstd * sc0.x + bi0.x,
                                (a.y - mean) * rstd * sc0.y + bi0.y);
    p0.h[1] = __floats2half2_rn((a.z - mean) * rstd * sc0.z + bi0.z,
                                (a.w - mean) * rstd * sc0.w + bi0.w);
    p1.h[0] = __floats2half2_rn((b.x - mean) * rstd * sc1.x + bi1.x,
                                (b.y - mean) * rstd * sc1.y + bi1.y);
    p1.h[1] = __floats2half2_rn((b.z - mean) * rstd * sc1.z + bi1.z,
                                (b.w - mean) * rstd * sc1.w + bi1.w);
    *(uint2*)&orow[tid * 4]         = p0.u;
    *(uint2*)&orow[(tid + 256) * 4] = p1.u;
}

// ---------------- shared GEMM tiling constants ----------------
#define GBN  256
#define GKS  32
#define GSA  40
#define GSB  40
#define GASZ (128 * GSA)
#define GBSZ (GBN * GSB)
#define SMEM_H256 ((2 * GASZ + 2 * GBSZ) * 2)

// mainloop macro body shared by both GEMM kernels ------------------------
// requires: sbase, tid, lane, w, wm, wn, Arow, Brow, K, acc declared.
#define GEMM_MAINLOOP()                                                        \
    auto loadA = [&](int st, int k0) {                                         \
        uint32_t abase = sbase + st * GASZ * 2;                                \
        _Pragma("unroll")                                                      \
        for (int i = 0; i < 2; i++) {                                          \
            int ch = tid + i * 256;                                            \
            int m = ch >> 2, kc = (ch & 3) << 3;                               \
            cp16(abase + (uint32_t)(m * GSA + kc) * 2,                         \
                 Arow + (size_t)m * K + k0 + kc);                              \
        }                                                                      \
    };                                                                         \
    auto loadB = [&](int st, int k0) {                                         \
        uint32_t bbase = sbase + (2 * GASZ + st * GBSZ) * 2;                   \
        _Pragma("unroll")                                                      \
        for (int i = 0; i < 4; i++) {                                          \
            int ch = tid + i * 256;                                            \
            int n = ch >> 2, kc = (ch & 3) << 3;                               \
            cp16(bbase + (uint32_t)(n * GSB + kc) * 2,                         \
                 Brow + (size_t)n * K + k0 + kc);                              \
        }                                                                      \
    };                                                                         \
    uint32_t aoff = ((uint32_t)((wm + (lane & 15)) * GSA + (lane >> 4) * 8)) * 2; \
    uint32_t boff = ((uint32_t)(2 * GASZ) +                                    \
        (uint32_t)((wn + (lane >> 4) * 8 + (lane & 7)) * GSB +                 \
                   ((lane >> 3) & 1) * 8)) * 2;                                \
    loadA(0, 0); loadB(0, 0); CP_COMMIT();                                     \
    int T = K / GKS;                                                           \
    for (int t = 0; t < T; t++) {                                              \
        if (t + 1 < T) {                                                       \
            loadA((t + 1) & 1, (t + 1) * GKS);                                 \
            loadB((t + 1) & 1, (t + 1) * GKS);                                 \
            CP_COMMIT(); CP_WAIT(1);                                           \
        } else { CP_WAIT(0); }                                                 \
        __syncthreads();                                                       \
        uint32_t aa = sbase + aoff + (uint32_t)((t & 1) * GASZ) * 2;           \
        uint32_t bb = sbase + boff + (uint32_t)((t & 1) * GBSZ) * 2;           \
        _Pragma("unroll")                                                      \
        for (int kk = 0; kk < GKS; kk += 16) {                                 \
            uint32_t af[4][4];                                                 \
            _Pragma("unroll")                                                  \
            for (int mi = 0; mi < 4; mi++)                                     \
                LDSM4(af[mi][0], af[mi][1], af[mi][2], af[mi][3],              \
                      aa + (uint32_t)(kk * 2) + (uint32_t)(mi * 16 * GSA * 2));\
            uint32_t bf[8][2];                                                 \
            _Pragma("unroll")                                                  \
            for (int np = 0; np < 4; np++)                                     \
                LDSM4(bf[2*np][0], bf[2*np][1], bf[2*np+1][0], bf[2*np+1][1],  \
                      bb + (uint32_t)(kk * 2) + (uint32_t)(np * 16 * GSB * 2));\
            _Pragma("unroll")                                                  \
            for (int mi = 0; mi < 4; mi++)                                     \
                _Pragma("unroll")                                              \
                for (int ni = 0; ni < 8; ni++)                                 \
                    mma_f16(acc[mi][ni], af[mi], bf[ni]);                      \
        }                                                                      \
        __syncthreads();                                                       \
    }

// ---------------- FP16 GEMM (generic epilogues) ----------------
// EPI: 1 = +bias+residual (float out), 2 = +bias -> GELU (half out)
template<int EPI>
__global__ __launch_bounds__(256) void hgemm(
    const __half* __restrict__ A, const __half* __restrict__ Bt,
    const float* __restrict__ bias, const float* __restrict__ res,
    void* __restrict__ Cv, int M, int N, int K)
{
    extern __shared__ __half smem[];
    uint32_t sbase = (uint32_t)__cvta_generic_to_shared(smem);
    int tid = threadIdx.x, lane = tid & 31, w = tid >> 5;
    int wm = (w >> 2) * 64, wn = (w & 3) * 64;
    int r = lane >> 2, cl = lane & 3;
    int bm = blockIdx.y * 128, bn = blockIdx.x * GBN;

    float acc[4][8][4];
    #pragma unroll
    for (int mi = 0; mi < 4; mi++)
        #pragma unroll
        for (int ni = 0; ni < 8; ni++)
            #pragma unroll
            for (int j = 0; j < 4; j++) acc[mi][ni][j] = 0.f;

    const __half* Arow = A + (size_t)bm * K;
    const __half* Brow = Bt + (size_t)bn * K;
    GEMM_MAINLOOP();

    #pragma unroll
    for (int mi = 0; mi < 4; mi++) {
        #pragma unroll
        for (int ni = 0; ni < 8; ni++) {
            int row0 = bm + wm + mi * 16 + r;
            int col  = bn + wn + ni * 8 + cl * 2;
            float2 bv = *(const float2*)&bias[col];
            #pragma unroll
            for (int hh = 0; hh < 2; hh++) {
                int row = row0 + hh * 8;
                float v0 = acc[mi][ni][hh * 2 + 0] + bv.x;
                float v1 = acc[mi][ni][hh * 2 + 1] + bv.y;
                if (EPI == 1) {
                    float2 rv = *(const float2*)&res[(size_t)row * N + col];
                    float* Cf = (float*)Cv;
                    *(float2*)&Cf[(size_t)row * N + col] =
                        make_float2(v0 + rv.x, v1 + rv.y);
                } else {
                    __half* Ch = (__half*)Cv;
                    *(__half2*)&Ch[(size_t)row * N + col] =
                        __floats2half2_rn(gelu_exact(v0), gelu_exact(v1));
                }
            }
        }
    }
}

// ---------------- Fused QKV GEMM (N = 2304, routing epilogue) ----------------
__global__ __launch_bounds__(256) void hgemm_qkv(
    const __half* __restrict__ A, const __half* __restrict__ Bt,
    const float* __restrict__ bias,
    __half* __restrict__ qo, __half* __restrict__ ko, __half* __restrict__ vo,
    int K, float qscale)
{
    extern __shared__ __half smem[];
    uint32_t sbase = (uint32_t)__cvta_generic_to_shared(smem);
    int tid = threadIdx.x, lane = tid & 31, w = tid >> 5;
    int wm = (w >> 2) * 64, wn = (w & 3) * 64;
    int r = lane >> 2, cl = lane & 3;
    int bm = blockIdx.y * 128, bn = blockIdx.x * GBN;

    float acc[4][8][4];
    #pragma unroll
    for (int mi = 0; mi < 4; mi++)
        #pragma unroll
        for (int ni = 0; ni < 8; ni++)
            #pragma unroll
            for (int j = 0; j < 4; j++) acc[mi][ni][j] = 0.f;

    const __half* Arow = A + (size_t)bm * K;
    const __half* Brow = Bt + (size_t)bn * K;
    GEMM_MAINLOOP();

    #pragma unroll
    for (int mi = 0; mi < 4; mi++) {
        #pragma unroll
        for (int ni = 0; ni < 8; ni++) {
            int row0 = bm + wm + mi * 16 + r;
            int col  = bn + wn + ni * 8 + cl * 2;
            float2 bv = *(const float2*)&bias[col];
            #pragma unroll
            for (int hh = 0; hh < 2; hh++) {
                int row = row0 + hh * 8;
                float v0 = acc[mi][ni][hh * 2 + 0] + bv.x;
                float v1 = acc[mi][ni][hh * 2 + 1] + bv.y;
                if (col < DMODEL) {
                    *(__half2*)&qo[(size_t)row * DMODEL + col] =
                        __floats2half2_rn(v0 * qscale, v1 * qscale);
                } else if (col < DMODEL + HDIM) {
                    *(__half2*)&ko[(size_t)row * HDIM + (col - DMODEL)] =
                        __floats2half2_rn(v0, v1);
                } else {
                    *(__half2*)&vo[(size_t)row * HDIM + (col - DMODEL - HDIM)] =
                        __floats2half2_rn(v0, v1);
                }
            }
        }
    }
}

// ---------------- FP16 tensor-core flash attention ----------------
#define SQ  136
#define SVT 72
#define FA_SMEM ((128*SQ + 2*64*SQ + 2*128*SVT) * 2)

__global__ __launch_bounds__(256) void fattn(
    const __half* __restrict__ q, const __half* __restrict__ k,
    const __half* __restrict__ vt, __half* __restrict__ o)
{
    extern __shared__ __half sm2[];
    __half* Qs = sm2;                    // [128][SQ]
    uint32_t qb  = (uint32_t)__cvta_generic_to_shared(Qs);
    uint32_t kbb = qb + 128 * SQ * 2;    // [2][64][SQ]
    uint32_t vbb = kbb + 2 * 64 * SQ * 2;// [2][128][SVT]

    int tid = threadIdx.x, lane = tid & 31, w = tid >> 5;
    int qt = (int)gridDim.x - 1 - (int)blockIdx.x;
    int bh = blockIdx.y, b = bh >> 4, h = bh & 15;
    int qs0 = qt * 128;
    int r = lane >> 2, cl = lane & 3;
    int m0 = w * 16;

    const __half* qp = q + ((size_t)(b * SEQ + qs0) * NHEAD + h) * HDIM;
    #pragma unroll
    for (int i = 0; i < 8; i++) {
        int ch = tid + i * 256; int rr = ch >> 4, c = (ch & 15) * 8;
        cp16(qb + (uint32_t)(rr * SQ + c) * 2, qp + (size_t)rr * (NHEAD * HDIM) + c);
    }

    auto loadKV = [&](int st, int kt) {
        int ks0 = kt * 64;
        const __half* kp = k + ((size_t)b * SEQ + ks0) * HDIM;
        uint32_t kbs = kbb + (uint32_t)st * 64 * SQ * 2;
        #pragma unroll
        for (int i = 0; i < 4; i++) {
            int ch = tid + i * 256; int rr = ch >> 4, c = (ch & 15) * 8;
            cp16(kbs + (uint32_t)(rr * SQ + c) * 2, kp + (size_t)rr * HDIM + c);
        }
        const __half* vp = vt + (size_t)b * HDIM * SEQ + ks0;
        uint32_t vbs = vbb + (uint32_t)st * 128 * SVT * 2;
        #pragma unroll
        for (int i = 0; i < 4; i++) {
            int ch = tid + i * 256; int rr = ch >> 3, c = (ch & 7) * 8;
            cp16(vbs + (uint32_t)(rr * SVT + c) * 2, vp + (size_t)rr * SEQ + c);
        }
    };

    loadKV(0, 0);
    CP_COMMIT();

    // ldmatrix per-thread offsets
    uint32_t qaddr = qb + (uint32_t)((m0 + (lane & 15)) * SQ + (lane >> 4) * 8) * 2;
    uint32_t koff  = (uint32_t)(((lane >> 4) * 8 + (lane & 7)) * SQ +
                                ((lane >> 3) & 1) * 8) * 2;
    uint32_t voff  = (uint32_t)(((lane >> 4) * 8 + (lane & 7)) * SVT +
                                ((lane >> 3) & 1) * 8) * 2;

    float m_0 = -1e30f, m_1 = -1e30f, l_0 = 0.f, l_1 = 0.f;
    float oacc[16][4];
    #pragma unroll
    for (int di = 0; di < 16; di++)
        #pragma unroll
        for (int j = 0; j < 4; j++) oacc[di][j] = 0.f;

    int nkt = 2 * (qt + 1);
    for (int kt = 0; kt < nkt; kt++) {
        CP_WAIT(0);
        __syncthreads();
        if (kt + 1 < nkt) { loadKV((kt + 1) & 1, kt + 1); CP_COMMIT(); }
        uint32_t ka = kbb + (uint32_t)((kt & 1) * 64 * SQ) * 2 + koff;
        uint32_t va = vbb + (uint32_t)((kt & 1) * 128 * SVT) * 2 + voff;

        // S = Q K^T
        float sacc[8][4];
        #pragma unroll
        for (int ni = 0; ni < 8; ni++)
            #pragma unroll
            for (int j = 0; j < 4; j++) sacc[ni][j] = 0.f;

        #pragma unroll
        for (int kk = 0; kk < 128; kk += 16) {
            uint32_t af[4];
            LDSM4(af[0], af[1], af[2], af[3], qaddr + (uint32_t)(kk * 2));
            uint32_t bf[8][2];
            #pragma unroll
            for (int np = 0; np < 4; np++)
                LDSM4(bf[2*np][0], bf[2*np][1], bf[2*np+1][0], bf[2*np+1][1],
                      ka + (uint32_t)(kk * 2) + (uint32_t)(np * 16 * SQ * 2));
            #pragma unroll
            for (int ni = 0; ni < 8; ni++)
                mma_f16(sacc[ni], af, bf[ni]);
        }

        // causal mask (diagonal region only)
        int ks0 = kt * 64;
        if (ks0 + 63 > qs0 + m0) {
            int row0 = qs0 + m0 + r, row1 = row0 + 8;
            #pragma unroll
            for (int ni = 0; ni < 8; ni++) {
                int c0 = ks0 + ni * 8 + cl * 2, c1 = c0 + 1;
                if (c0 > row0) sacc[ni][0] = -1e30f;
                if (c1 > row0) sacc[ni][1] = -1e30f;
                if (c0 > row1) sacc[ni][2] = -1e30f;
                if (c1 > row1) sacc[ni][3] = -1e30f;
            }
        }

        // online softmax
        float mx0 = -1e30f, mx1 = -1e30f;
        #pragma unroll
        for (int ni = 0; ni < 8; ni++) {
            mx0 = fmaxf(mx0, fmaxf(sacc[ni][0], sacc[ni][1]));
            mx1 = fmaxf(mx1, fmaxf(sacc[ni][2], sacc[ni][3]));
        }
        mx0 = fmaxf(mx0, __shfl_xor_sync(0xffffffffu, mx0, 1));
        mx0 = fmaxf(mx0, __shfl_xor_sync(0xffffffffu, mx0, 2));
        mx1 = fmaxf(mx1, __shfl_xor_sync(0xffffffffu, mx1, 1));
        mx1 = fmaxf(mx1, __shfl_xor_sync(0xffffffffu, mx1, 2));
        float mn0 = fmaxf(m_0, mx0), mn1 = fmaxf(m_1, mx1);
        float a0 = __expf(m_0 - mn0), a1 = __expf(m_1 - mn1);
        float s0 = 0.f, s1 = 0.f;
        #pragma unroll
        for (int ni = 0; ni < 8; ni++) {
            sacc[ni][0] = __expf(sacc[ni][0] - mn0);
            sacc[ni][1] = __expf(sacc[ni][1] - mn0);
            sacc[ni][2] = __expf(sacc[ni][2] - mn1);
            sacc[ni][3] = __expf(sacc[ni][3] - mn1);
            s0 += sacc[ni][0] + sacc[ni][1];
            s1 += sacc[ni][2] + sacc[ni][3];
        }
        s0 += __shfl_xor_sync(0xffffffffu, s0, 1);
        s0 += __shfl_xor_sync(0xffffffffu, s0, 2);
        s1 += __shfl_xor_sync(0xffffffffu, s1, 1);
        s1 += __shfl_xor_sync(0xffffffffu, s1, 2);
        l_0 = l_0 * a0 + s0; l_1 = l_1 * a1 + s1;
        m_0 = mn0; m_1 = mn1;
        #pragma unroll
        for (int di = 0; di < 16; di++) {
            oacc[di][0] *= a0; oacc[di][1] *= a0;
            oacc[di][2] *= a1; oacc[di][3] *= a1;
        }

        // P fragments (registers -> A-frag)
        uint32_t pa[4][4];
        #pragma unroll
        for (int j = 0; j < 4; j++) {
            pa[j][0] = packh2(sacc[2*j  ][0], sacc[2*j  ][1]);
            pa[j][1] = packh2(sacc[2*j  ][2], sacc[2*j  ][3]);
            pa[j][2] = packh2(sacc[2*j+1][0], sacc[2*j+1][1]);
            pa[j][3] = packh2(sacc[2*j+1][2], sacc[2*j+1][3]);
        }

        // O += P V
        #pragma unroll
        for (int j = 0; j < 4; j++) {
            #pragma unroll
            for (int dp = 0; dp < 8; dp++) {
                uint32_t bf[4];
                LDSM4(bf[0], bf[1], bf[2], bf[3],
                      va + (uint32_t)(j * 16 * 2) + (uint32_t)(dp * 16 * SVT * 2));
                mma_f16(oacc[2*dp    ], pa[j], bf    );
                mma_f16(oacc[2*dp + 1], pa[j], bf + 2);
            }
        }
    }

    // epilogue
    float i0 = 1.f / l_0, i1 = 1.f / l_1;
    __half* op = o + ((size_t)(b * SEQ + qs0 + m0) * NHEAD + h) * HDIM;
    #pragma unroll
    for (int di = 0; di < 16; di++) {
        int c = di * 8 + cl * 2;
        *(__half2*)&op[(size_t)r * (NHEAD * HDIM) + c] =
            __floats2half2_rn(oacc[di][0] * i0, oacc[di][1] * i0);
        *(__half2*)&op[(size_t)(r + 8) * (NHEAD * HDIM) + c] =
            __floats2half2_rn(oacc[di][2] * i1, oacc[di][3] * i1);
    }
}

// ---------------- launch ----------------
extern "C" void kernel_launch(void* const* d_in, const int* in_sizes, int n_in,
                              void* d_out, int out_size)
{
    const float* x     = (const float*)d_in[0];
    const float* wq    = (const float*)d_in[2];
    const float* wq_b  = (const float*)d_in[3];
    const float* wk    = (const float*)d_in[4];
    const float* wk_b  = (const float*)d_in[5];
    const float* wv    = (const float*)d_in[6];
    const float* wv_b  = (const float*)d_in[7];
    const float* wo    = (const float*)d_in[8];
    const float* wo_b  = (const float*)d_in[9];
    const float* w1    = (const float*)d_in[10];
    const float* w1_b  = (const float*)d_in[11];
    const float* w2    = (const float*)d_in[12];
    const float* w2_b  = (const float*)d_in[13];
    const float* ln1_s = (const float*)d_in[14];
    const float* ln1_b = (const float*)d_in[15];
    const float* ln2_s = (const float*)d_in[16];
    const float* ln2_b = (const float*)d_in[17];
    float* out = (float*)d_out;

    __half *hh, *qh, *kh, *vh, *vtp, *oh, *ffh;
    __half *cwqkv, *cwo, *cw1, *cw2;
    float  *x1, *bqkv;
    cudaGetSymbolAddress((void**)&hh,    g_hh);
    cudaGetSymbolAddress((void**)&qh,    g_qh);
    cudaGetSymbolAddress((void**)&kh,    g_kh);
    cudaGetSymbolAddress((void**)&vh,    g_vh);
    cudaGetSymbolAddress((void**)&vtp,   g_vt);
    cudaGetSymbolAddress((void**)&oh,    g_oh);
    cudaGetSymbolAddress((void**)&x1,    g_x1);
    cudaGetSymbolAddress((void**)&ffh,   g_ffh);
    cudaGetSymbolAddress((void**)&cwqkv, g_wqkv);
    cudaGetSymbolAddress((void**)&bqkv,  g_bqkv);
    cudaGetSymbolAddress((void**)&cwo,   g_wo);
    cudaGetSymbolAddress((void**)&cw1,   g_w1);
    cudaGetSymbolAddress((void**)&cw2,   g_w2);

    cudaFuncSetAttribute(fattn, cudaFuncAttributeMaxDynamicSharedMemorySize, FA_SMEM);
    cudaFuncSetAttribute(hgemm<1>, cudaFuncAttributeMaxDynamicSharedMemorySize, SMEM_H256);
    cudaFuncSetAttribute(hgemm<2>, cudaFuncAttributeMaxDynamicSharedMemorySize, SMEM_H256);
    cudaFuncSetAttribute(hgemm_qkv, cudaFuncAttributeMaxDynamicSharedMemorySize, SMEM_H256);

    // transpose + half-cvt the weights: [K,N] -> [N,K]; QKV fused buffer
    transpose_cvt<<<dim3(DMODEL/32, DMODEL/32), 256>>>(wq, cwqkv, DMODEL, DMODEL);
    transpose_cvt<<<dim3(HDIM/32,   DMODEL/32), 256>>>(wk, cwqkv + (size_t)DMODEL * DMODEL,
                                                       DMODEL, HDIM);
    transpose_cvt<<<dim3(HDIM/32,   DMODEL/32), 256>>>(wv, cwqkv + (size_t)(DMODEL + HDIM) * DMODEL,
                                                       DMODEL, HDIM);
    transpose_cvt<<<dim3(DMODEL/32, DMODEL/32), 256>>>(wo, cwo, DMODEL, DMODEL);
    transpose_cvt<<<dim3(FFDIM/32,  DMODEL/32), 256>>>(w1, cw1, DMODEL, FFDIM);
    transpose_cvt<<<dim3(DMODEL/32, FFDIM/32),  256>>>(w2, cw2, FFDIM, DMODEL);
    fill_bqkv<<<9, 256>>>(wq_b, wk_b, wv_b, bqkv);

    const float qscale = 0.08838834764831845f;  // 1/sqrt(128)

    // h = LN1(x)  (half)
    ln_kernel<<<MTOK, 256>>>(x, ln1_s, ln1_b, hh);
    // fused QKV projection
    hgemm_qkv<<<dim3(NQKV/GBN, MTOK/128), 256, SMEM_H256>>>(
        hh, cwqkv, bqkv, qh, kh, vh, DMODEL, qscale);
    // V transpose
    vtrans<<<dim3(HDIM/32, SEQ/32, 2), 256>>>(vh, vtp);
    // attention (half out)
    fattn<<<dim3(SEQ/128, 2*NHEAD), 256, FA_SMEM>>>(qh, kh, vtp, oh);
    // x1 = x + O @ wo + wo_b  (float out)
    hgemm<1><<<dim3(DMODEL/GBN, MTOK/128), 256, SMEM_H256>>>(
        oh, cwo, wo_b, x, x1, MTOK, DMODEL, DMODEL);
    // h = LN2(x1) (half)
    ln_kernel<<<MTOK, 256>>>(x1, ln2_s, ln2_b, hh);
    // ff = gelu(h @ w1 + w1_b)  (half out)
    hgemm<2><<<dim3(FFDIM/GBN, MTOK/128), 256, SMEM_H256>>>(
        hh, cw1, w1_b, nullptr, ffh, MTOK, FFDIM, DMODEL);
    // out = x1 + ff @ w2 + w2_b (float out)
    hgemm<1><<<dim3(DMODEL/GBN, MTOK/128), 256, SMEM_H256>>>(
        ffh, cw2, w2_b, x1, out, MTOK, DMODEL, FFDIM);
}

// round 8
// speedup vs baseline: 6.1818x; 1.0029x over previous
#include <cuda_runtime.h>
#include <cuda_fp16.h>
#include <math.h>
#include <stdint.h>

// Problem dims
#define MTOK   4096      // B*S
#define DMODEL 2048
#define NHEAD  16
#define HDIM   128
#define FFDIM  8192
#define SEQ    2048
#define NQKV   2304      // 2048 + 128 + 128

// ---------------- scratch (device globals: allocation-free) ----------------
__device__ __half g_hh [MTOK * DMODEL];          // LN output (half)
__device__ __half g_qh [MTOK * DMODEL];          // Q half (pre-scaled)
__device__ __half g_kh [MTOK * HDIM];            // K half
__device__ __half g_vh [MTOK * HDIM];            // V half
__device__ __half g_vt [2 * HDIM * SEQ];         // V transposed [B][HD][S]
__device__ __half g_oh [MTOK * DMODEL];          // attn O (half)
__device__ float  g_x1 [MTOK * DMODEL];          // x + attn_out
__device__ __half g_ffh[(size_t)MTOK * FFDIM];   // FF1 output (half)
// transposed ([K,N] -> [N,K]) half weights
__device__ __half g_wqkv[(size_t)NQKV * DMODEL]; // [Q;K;V] rows
__device__ float  g_bqkv[NQKV];
__device__ __half g_wo[DMODEL * DMODEL];
__device__ __half g_w1[(size_t)DMODEL * FFDIM];
__device__ __half g_w2[(size_t)FFDIM * DMODEL];

// ---------------- helpers ----------------
__device__ __forceinline__ float gelu_exact(float x) {
    return 0.5f * x * (1.0f + erff(x * 0.70710678118654752f));
}
__device__ __forceinline__ void cp16(uint32_t saddr, const void* g) {
    asm volatile("cp.async.cg.shared.global [%0], [%1], 16;" :: "r"(saddr), "l"(g));
}
#define CP_COMMIT() asm volatile("cp.async.commit_group;\n")
#define CP_WAIT(n)  asm volatile("cp.async.wait_group %0;\n" :: "n"(n))

__device__ __forceinline__ void mma_f16(float* c, const uint32_t* a, const uint32_t* b) {
    asm volatile(
        "mma.sync.aligned.m16n8k16.row.col.f32.f16.f16.f32 "
        "{%0,%1,%2,%3}, {%4,%5,%6,%7}, {%8,%9}, {%0,%1,%2,%3};\n"
        : "+f"(c[0]), "+f"(c[1]), "+f"(c[2]), "+f"(c[3])
        : "r"(a[0]), "r"(a[1]), "r"(a[2]), "r"(a[3]), "r"(b[0]), "r"(b[1]));
}
#define LDSM4(r0, r1, r2, r3, addr) \
    asm volatile("ldmatrix.sync.aligned.m8n8.x4.shared.b16 {%0,%1,%2,%3}, [%4];" \
        : "=r"(r0), "=r"(r1), "=r"(r2), "=r"(r3) : "r"(addr))

__device__ __forceinline__ uint32_t packh2(float x, float y) {
    __half2 t = __floats2half2_rn(x, y);
    return *(uint32_t*)&t;
}

// ---------------- weight transpose + half cvt: [K,N] -> [N,K] ----------
__global__ __launch_bounds__(256) void transpose_cvt(
    const float* __restrict__ in, __half* __restrict__ out, int K, int N)
{
    __shared__ float t[32][33];
    int bx = blockIdx.x * 32, by = blockIdx.y * 32;
    int tx = threadIdx.x & 31, ty = threadIdx.x >> 5;
    #pragma unroll
    for (int i = 0; i < 32; i += 8)
        t[ty + i][tx] = in[(size_t)(by + ty + i) * N + bx + tx];
    __syncthreads();
    #pragma unroll
    for (int i = 0; i < 32; i += 8)
        out[(size_t)(bx + ty + i) * K + by + tx] = __float2half(t[tx][ty + i]);
}

__global__ void fill_bqkv(const float* __restrict__ qb, const float* __restrict__ kb,
                          const float* __restrict__ vb, float* __restrict__ o)
{
    int i = blockIdx.x * 256 + threadIdx.x;
    if (i < DMODEL) o[i] = qb[i];
    else if (i < DMODEL + HDIM) o[i] = kb[i - DMODEL];
    else if (i < NQKV) o[i] = vb[i - DMODEL - HDIM];
}

// ---------------- V transpose (half): [B*S, HD] -> [B][HD][S] ----------
__global__ __launch_bounds__(256) void vtrans(
    const __half* __restrict__ in, __half* __restrict__ out)
{
    __shared__ __half t[32][34];
    int b = blockIdx.z;
    int d0 = blockIdx.x * 32, s0 = blockIdx.y * 32;
    int tx = threadIdx.x & 31, ty = threadIdx.x >> 5;
    #pragma unroll
    for (int i = 0; i < 32; i += 8)
        t[ty + i][tx] = in[(size_t)(b * SEQ + s0 + ty + i) * HDIM + d0 + tx];
    __syncthreads();
    #pragma unroll
    for (int i = 0; i < 32; i += 8)
        out[(size_t)(b * HDIM + d0 + ty + i) * SEQ + s0 + tx] = t[tx][ty + i];
}

// ---------------- LayerNorm (half output) ----------------
__global__ __launch_bounds__(256) void ln_kernel(
    const float* __restrict__ x, const float* __restrict__ sc,
    const float* __restrict__ bi, __half* __restrict__ out)
{
    int row = blockIdx.x, tid = threadIdx.x;
    const float4* xr = (const float4*)(x + (size_t)row * DMODEL);
    float4 a = xr[tid];
    float4 b = xr[tid + 256];
    float s  = a.x + a.y + a.z + a.w + b.x + b.y + b.z + b.w;
    float ss = a.x*a.x + a.y*a.y + a.z*a.z + a.w*a.w
             + b.x*b.x + b.y*b.y + b.z*b.z + b.w*b.w;
    __shared__ float rs[8], rss[8];
    #pragma unroll
    for (int off = 16; off; off >>= 1) {
        s  += __shfl_xor_sync(0xffffffffu, s,  off);
        ss += __shfl_xor_sync(0xffffffffu, ss, off);
    }
    if ((tid & 31) == 0) { rs[tid >> 5] = s; rss[tid >> 5] = ss; }
    __syncthreads();
    float tot = 0.f, tot2 = 0.f;
    #pragma unroll
    for (int i = 0; i < 8; i++) { tot += rs[i]; tot2 += rss[i]; }
    float mean = tot * (1.0f / DMODEL);
    float var  = tot2 * (1.0f / DMODEL) - mean * mean;
    float rstd = rsqrtf(var + 1e-5f);

    const float4* s4 = (const float4*)sc;
    const float4* b4 = (const float4*)bi;
    float4 sc0 = s4[tid], bi0 = b4[tid], sc1 = s4[tid + 256], bi1 = b4[tid + 256];
    __half* orow = out + (size_t)row * DMODEL;
    union { uint2 u; __half2 h[2]; } p0, p1;
    p0.h[0] = __floats2half2_rn((a.x - mean) * rstd * sc0.x + bi0.x,
                                (a.y - mean) * rstd * sc0.y + bi0.y);
    p0.h[1] = __floats2half2_rn((a.z - mean) * rstd * sc0.z + bi0.z,
                                (a.w - mean) * rstd * sc0.w + bi0.w);
    p1.h[0] = __floats2half2_rn((b.x - mean) * rstd * sc1.x + bi1.x,
                                (b.y - mean) * rstd * sc1.y + bi1.y);
    p1.h[1] = __floats2half2_rn((b.z - mean) * rstd * sc1.z + bi1.z,
                                (b.w - mean) * rstd * sc1.w + bi1.w);
    *(uint2*)&orow[tid * 4]         = p0.u;
    *(uint2*)&orow[(tid + 256) * 4] = p1.u;
}

// ---------------- shared GEMM tiling constants ----------------
#define GBN  256
#define GKS  32
#define GST  4        // pipeline stages
#define GSA  40
#define GSB  40
#define GASZ (128 * GSA)
#define GBSZ (GBN * GSB)
#define GSTSZ (GASZ + GBSZ)
#define SMEM_H256 (GST * GSTSZ * 2)   // 122880 bytes

// 4-stage single-sync mainloop shared by both GEMM kernels -----------------
// requires: sbase, tid, lane, w, wm, wn, Arow, Brow, K, acc declared.
#define GEMM_MAINLOOP()                                                        \
    auto loadStage = [&](int slot, int k0) {                                   \
        uint32_t abase = sbase + (uint32_t)(slot * GSTSZ) * 2;                 \
        uint32_t bbase = abase + (uint32_t)GASZ * 2;                           \
        _Pragma("unroll")                                                      \
        for (int i = 0; i < 2; i++) {                                          \
            int ch = tid + i * 256;                                            \
            int m = ch >> 2, kc = (ch & 3) << 3;                               \
            cp16(abase + (uint32_t)(m * GSA + kc) * 2,                         \
                 Arow + (size_t)m * K + k0 + kc);                              \
        }                                                                      \
        _Pragma("unroll")                                                      \
        for (int i = 0; i < 4; i++) {                                          \
            int ch = tid + i * 256;                                            \
            int n = ch >> 2, kc = (ch & 3) << 3;                               \
            cp16(bbase + (uint32_t)(n * GSB + kc) * 2,                         \
                 Brow + (size_t)n * K + k0 + kc);                              \
        }                                                                      \
    };                                                                         \
    uint32_t aoff = ((uint32_t)((wm + (lane & 15)) * GSA + (lane >> 4) * 8)) * 2; \
    uint32_t boff = ((uint32_t)GASZ +                                          \
        (uint32_t)((wn + (lane >> 4) * 8 + (lane & 7)) * GSB +                 \
                   ((lane >> 3) & 1) * 8)) * 2;                                \
    loadStage(0, 0); CP_COMMIT();                                              \
    loadStage(1, GKS); CP_COMMIT();                                            \
    loadStage(2, 2 * GKS); CP_COMMIT();                                        \
    int T = K / GKS;                                                           \
    for (int t = 0; t < T; t++) {                                              \
        CP_WAIT(2);                                                            \
        __syncthreads();                                                       \
        if (t + 3 < T) { loadStage((t + 3) & 3, (t + 3) * GKS); }              \
        CP_COMMIT();                                                           \
        uint32_t aa = sbase + (uint32_t)((t & 3) * GSTSZ) * 2 + aoff;          \
        uint32_t bb = sbase + (uint32_t)((t & 3) * GSTSZ) * 2 + boff;          \
        _Pragma("unroll")                                                      \
        for (int kk = 0; kk < GKS; kk += 16) {                                 \
            uint32_t af[4][4];                                                 \
            _Pragma("unroll")                                                  \
            for (int mi = 0; mi < 4; mi++)                                     \
                LDSM4(af[mi][0], af[mi][1], af[mi][2], af[mi][3],              \
                      aa + (uint32_t)(kk * 2) + (uint32_t)(mi * 16 * GSA * 2));\
            uint32_t bf[8][2];                                                 \
            _Pragma("unroll")                                                  \
            for (int np = 0; np < 4; np++)                                     \
                LDSM4(bf[2*np][0], bf[2*np][1], bf[2*np+1][0], bf[2*np+1][1],  \
                      bb + (uint32_t)(kk * 2) + (uint32_t)(np * 16 * GSB * 2));\
            _Pragma("unroll")                                                  \
            for (int mi = 0; mi < 4; mi++)                                     \
                _Pragma("unroll")                                              \
                for (int ni = 0; ni < 8; ni++)                                 \
                    mma_f16(acc[mi][ni], af[mi], bf[ni]);                      \
        }                                                                      \
    }

// ---------------- FP16 GEMM (generic epilogues) ----------------
// EPI: 1 = +bias+residual (float out), 2 = +bias -> GELU (half out)
template<int EPI>
__global__ __launch_bounds__(256) void hgemm(
    const __half* __restrict__ A, const __half* __restrict__ Bt,
    const float* __restrict__ bias, const float* __restrict__ res,
    void* __restrict__ Cv, int M, int N, int K)
{
    extern __shared__ __half smem[];
    uint32_t sbase = (uint32_t)__cvta_generic_to_shared(smem);
    int tid = threadIdx.x, lane = tid & 31, w = tid >> 5;
    int wm = (w >> 2) * 64, wn = (w & 3) * 64;
    int r = lane >> 2, cl = lane & 3;
    int bm = blockIdx.y * 128, bn = blockIdx.x * GBN;

    float acc[4][8][4];
    #pragma unroll
    for (int mi = 0; mi < 4; mi++)
        #pragma unroll
        for (int ni = 0; ni < 8; ni++)
            #pragma unroll
            for (int j = 0; j < 4; j++) acc[mi][ni][j] = 0.f;

    const __half* Arow = A + (size_t)bm * K;
    const __half* Brow = Bt + (size_t)bn * K;
    GEMM_MAINLOOP();

    #pragma unroll
    for (int mi = 0; mi < 4; mi++) {
        #pragma unroll
        for (int ni = 0; ni < 8; ni++) {
            int row0 = bm + wm + mi * 16 + r;
            int col  = bn + wn + ni * 8 + cl * 2;
            float2 bv = *(const float2*)&bias[col];
            #pragma unroll
            for (int hh = 0; hh < 2; hh++) {
                int row = row0 + hh * 8;
                float v0 = acc[mi][ni][hh * 2 + 0] + bv.x;
                float v1 = acc[mi][ni][hh * 2 + 1] + bv.y;
                if (EPI == 1) {
                    float2 rv = *(const float2*)&res[(size_t)row * N + col];
                    float* Cf = (float*)Cv;
                    *(float2*)&Cf[(size_t)row * N + col] =
                        make_float2(v0 + rv.x, v1 + rv.y);
                } else {
                    __half* Ch = (__half*)Cv;
                    *(__half2*)&Ch[(size_t)row * N + col] =
                        __floats2half2_rn(gelu_exact(v0), gelu_exact(v1));
                }
            }
        }
    }
}

// ---------------- Fused QKV GEMM (N = 2304, routing epilogue) ----------------
__global__ __launch_bounds__(256) void hgemm_qkv(
    const __half* __restrict__ A, const __half* __restrict__ Bt,
    const float* __restrict__ bias,
    __half* __restrict__ qo, __half* __restrict__ ko, __half* __restrict__ vo,
    int K, float qscale)
{
    extern __shared__ __half smem[];
    uint32_t sbase = (uint32_t)__cvta_generic_to_shared(smem);
    int tid = threadIdx.x, lane = tid & 31, w = tid >> 5;
    int wm = (w >> 2) * 64, wn = (w & 3) * 64;
    int r = lane >> 2, cl = lane & 3;
    int bm = blockIdx.y * 128, bn = blockIdx.x * GBN;

    float acc[4][8][4];
    #pragma unroll
    for (int mi = 0; mi < 4; mi++)
        #pragma unroll
        for (int ni = 0; ni < 8; ni++)
            #pragma unroll
            for (int j = 0; j < 4; j++) acc[mi][ni][j] = 0.f;

    const __half* Arow = A + (size_t)bm * K;
    const __half* Brow = Bt + (size_t)bn * K;
    GEMM_MAINLOOP();

    #pragma unroll
    for (int mi = 0; mi < 4; mi++) {
        #pragma unroll
        for (int ni = 0; ni < 8; ni++) {
            int row0 = bm + wm + mi * 16 + r;
            int col  = bn + wn + ni * 8 + cl * 2;
            float2 bv = *(const float2*)&bias[col];
            #pragma unroll
            for (int hh = 0; hh < 2; hh++) {
                int row = row0 + hh * 8;
                float v0 = acc[mi][ni][hh * 2 + 0] + bv.x;
                float v1 = acc[mi][ni][hh * 2 + 1] + bv.y;
                if (col < DMODEL) {
                    *(__half2*)&qo[(size_t)row * DMODEL + col] =
                        __floats2half2_rn(v0 * qscale, v1 * qscale);
                } else if (col < DMODEL + HDIM) {
                    *(__half2*)&ko[(size_t)row * HDIM + (col - DMODEL)] =
                        __floats2half2_rn(v0, v1);
                } else {
                    *(__half2*)&vo[(size_t)row * HDIM + (col - DMODEL - HDIM)] =
                        __floats2half2_rn(v0, v1);
                }
            }
        }
    }
}

// ---------------- FP16 tensor-core flash attention ----------------
#define SQ  136
#define SVT 72
#define FA_SMEM ((128*SQ + 2*64*SQ + 2*128*SVT) * 2)

__global__ __launch_bounds__(256) void fattn(
    const __half* __restrict__ q, const __half* __restrict__ k,
    const __half* __restrict__ vt, __half* __restrict__ o)
{
    extern __shared__ __half sm2[];
    __half* Qs = sm2;                    // [128][SQ]
    uint32_t qb  = (uint32_t)__cvta_generic_to_shared(Qs);
    uint32_t kbb = qb + 128 * SQ * 2;    // [2][64][SQ]
    uint32_t vbb = kbb + 2 * 64 * SQ * 2;// [2][128][SVT]

    int tid = threadIdx.x, lane = tid & 31, w = tid >> 5;
    int qt = (int)gridDim.x - 1 - (int)blockIdx.x;
    int bh = blockIdx.y, b = bh >> 4, h = bh & 15;
    int qs0 = qt * 128;
    int r = lane >> 2, cl = lane & 3;
    int m0 = w * 16;

    const __half* qp = q + ((size_t)(b * SEQ + qs0) * NHEAD + h) * HDIM;
    #pragma unroll
    for (int i = 0; i < 8; i++) {
        int ch = tid + i * 256; int rr = ch >> 4, c = (ch & 15) * 8;
        cp16(qb + (uint32_t)(rr * SQ + c) * 2, qp + (size_t)rr * (NHEAD * HDIM) + c);
    }

    auto loadKV = [&](int st, int kt) {
        int ks0 = kt * 64;
        const __half* kp = k + ((size_t)b * SEQ + ks0) * HDIM;
        uint32_t kbs = kbb + (uint32_t)st * 64 * SQ * 2;
        #pragma unroll
        for (int i = 0; i < 4; i++) {
            int ch = tid + i * 256; int rr = ch >> 4, c = (ch & 15) * 8;
            cp16(kbs + (uint32_t)(rr * SQ + c) * 2, kp + (size_t)rr * HDIM + c);
        }
        const __half* vp = vt + (size_t)b * HDIM * SEQ + ks0;
        uint32_t vbs = vbb + (uint32_t)st * 128 * SVT * 2;
        #pragma unroll
        for (int i = 0; i < 4; i++) {
            int ch = tid + i * 256; int rr = ch >> 3, c = (ch & 7) * 8;
            cp16(vbs + (uint32_t)(rr * SVT + c) * 2, vp + (size_t)rr * SEQ + c);
        }
    };

    loadKV(0, 0);
    CP_COMMIT();

    uint32_t qaddr = qb + (uint32_t)((m0 + (lane & 15)) * SQ + (lane >> 4) * 8) * 2;
    uint32_t koff  = (uint32_t)(((lane >> 4) * 8 + (lane & 7)) * SQ +
                                ((lane >> 3) & 1) * 8) * 2;
    uint32_t voff  = (uint32_t)(((lane >> 4) * 8 + (lane & 7)) * SVT +
                                ((lane >> 3) & 1) * 8) * 2;

    float m_0 = -1e30f, m_1 = -1e30f, l_0 = 0.f, l_1 = 0.f;
    float oacc[16][4];
    #pragma unroll
    for (int di = 0; di < 16; di++)
        #pragma unroll
        for (int j = 0; j < 4; j++) oacc[di][j] = 0.f;

    int nkt = 2 * (qt + 1);
    for (int kt = 0; kt < nkt; kt++) {
        CP_WAIT(0);
        __syncthreads();
        if (kt + 1 < nkt) { loadKV((kt + 1) & 1, kt + 1); CP_COMMIT(); }
        uint32_t ka = kbb + (uint32_t)((kt & 1) * 64 * SQ) * 2 + koff;
        uint32_t va = vbb + (uint32_t)((kt & 1) * 128 * SVT) * 2 + voff;

        // S = Q K^T
        float sacc[8][4];
        #pragma unroll
        for (int ni = 0; ni < 8; ni++)
            #pragma unroll
            for (int j = 0; j < 4; j++) sacc[ni][j] = 0.f;

        #pragma unroll
        for (int kk = 0; kk < 128; kk += 16) {
            uint32_t af[4];
            LDSM4(af[0], af[1], af[2], af[3], qaddr + (uint32_t)(kk * 2));
            uint32_t bf[8][2];
            #pragma unroll
            for (int np = 0; np < 4; np++)
                LDSM4(bf[2*np][0], bf[2*np][1], bf[2*np+1][0], bf[2*np+1][1],
                      ka + (uint32_t)(kk * 2) + (uint32_t)(np * 16 * SQ * 2));
            #pragma unroll
            for (int ni = 0; ni < 8; ni++)
                mma_f16(sacc[ni], af, bf[ni]);
        }

        // causal mask (diagonal region only)
        int ks0 = kt * 64;
        if (ks0 + 63 > qs0 + m0) {
            int row0 = qs0 + m0 + r, row1 = row0 + 8;
            #pragma unroll
            for (int ni = 0; ni < 8; ni++) {
                int c0 = ks0 + ni * 8 + cl * 2, c1 = c0 + 1;
                if (c0 > row0) sacc[ni][0] = -1e30f;
                if (c1 > row0) sacc[ni][1] = -1e30f;
                if (c0 > row1) sacc[ni][2] = -1e30f;
                if (c1 > row1) sacc[ni][3] = -1e30f;
            }
        }

        // online softmax
        float mx0 = -1e30f, mx1 = -1e30f;
        #pragma unroll
        for (int ni = 0; ni < 8; ni++) {
            mx0 = fmaxf(mx0, fmaxf(sacc[ni][0], sacc[ni][1]));
            mx1 = fmaxf(mx1, fmaxf(sacc[ni][2], sacc[ni][3]));
        }
        mx0 = fmaxf(mx0, __shfl_xor_sync(0xffffffffu, mx0, 1));
        mx0 = fmaxf(mx0, __shfl_xor_sync(0xffffffffu, mx0, 2));
        mx1 = fmaxf(mx1, __shfl_xor_sync(0xffffffffu, mx1, 1));
        mx1 = fmaxf(mx1, __shfl_xor_sync(0xffffffffu, mx1, 2));
        float mn0 = fmaxf(m_0, mx0), mn1 = fmaxf(m_1, mx1);
        float a0 = __expf(m_0 - mn0), a1 = __expf(m_1 - mn1);
        float s0 = 0.f, s1 = 0.f;
        #pragma unroll
        for (int ni = 0; ni < 8; ni++) {
            sacc[ni][0] = __expf(sacc[ni][0] - mn0);
            sacc[ni][1] = __expf(sacc[ni][1] - mn0);
            sacc[ni][2] = __expf(sacc[ni][2] - mn1);
            sacc[ni][3] = __expf(sacc[ni][3] - mn1);
            s0 += sacc[ni][0] + sacc[ni][1];
            s1 += sacc[ni][2] + sacc[ni][3];
        }
        s0 += __shfl_xor_sync(0xffffffffu, s0, 1);
        s0 += __shfl_xor_sync(0xffffffffu, s0, 2);
        s1 += __shfl_xor_sync(0xffffffffu, s1, 1);
        s1 += __shfl_xor_sync(0xffffffffu, s1, 2);
        l_0 = l_0 * a0 + s0; l_1 = l_1 * a1 + s1;
        m_0 = mn0; m_1 = mn1;
        #pragma unroll
        for (int di = 0; di < 16; di++) {
            oacc[di][0] *= a0; oacc[di][1] *= a0;
            oacc[di][2] *= a1; oacc[di][3] *= a1;
        }

        // P fragments (registers -> A-frag)
        uint32_t pa[4][4];
        #pragma unroll
        for (int j = 0; j < 4; j++) {
            pa[j][0] = packh2(sacc[2*j  ][0], sacc[2*j  ][1]);
            pa[j][1] = packh2(sacc[2*j  ][2], sacc[2*j  ][3]);
            pa[j][2] = packh2(sacc[2*j+1][0], sacc[2*j+1][1]);
            pa[j][3] = packh2(sacc[2*j+1][2], sacc[2*j+1][3]);
        }

        // O += P V
        #pragma unroll
        for (int j = 0; j < 4; j++) {
            #pragma unroll
            for (int dp = 0; dp < 8; dp++) {
                uint32_t bf[4];
                LDSM4(bf[0], bf[1], bf[2], bf[3],
                      va + (uint32_t)(j * 16 * 2) + (uint32_t)(dp * 16 * SVT * 2));
                mma_f16(oacc[2*dp    ], pa[j], bf    );
                mma_f16(oacc[2*dp + 1], pa[j], bf + 2);
            }
        }
    }

    // epilogue
    float i0 = 1.f / l_0, i1 = 1.f / l_1;
    __half* op = o + ((size_t)(b * SEQ + qs0 + m0) * NHEAD + h) * HDIM;
    #pragma unroll
    for (int di = 0; di < 16; di++) {
        int c = di * 8 + cl * 2;
        *(__half2*)&op[(size_t)r * (NHEAD * HDIM) + c] =
            __floats2half2_rn(oacc[di][0] * i0, oacc[di][1] * i0);
        *(__half2*)&op[(size_t)(r + 8) * (NHEAD * HDIM) + c] =
            __floats2half2_rn(oacc[di][2] * i1, oacc[di][3] * i1);
    }
}

// ---------------- launch ----------------
extern "C" void kernel_launch(void* const* d_in, const int* in_sizes, int n_in,
                              void* d_out, int out_size)
{
    const float* x     = (const float*)d_in[0];
    const float* wq    = (const float*)d_in[2];
    const float* wq_b  = (const float*)d_in[3];
    const float* wk    = (const float*)d_in[4];
    const float* wk_b  = (const float*)d_in[5];
    const float* wv    = (const float*)d_in[6];
    const float* wv_b  = (const float*)d_in[7];
    const float* wo    = (const float*)d_in[8];
    const float* wo_b  = (const float*)d_in[9];
    const float* w1    = (const float*)d_in[10];
    const float* w1_b  = (const float*)d_in[11];
    const float* w2    = (const float*)d_in[12];
    const float* w2_b  = (const float*)d_in[13];
    const float* ln1_s = (const float*)d_in[14];
    const float* ln1_b = (const float*)d_in[15];
    const float* ln2_s = (const float*)d_in[16];
    const float* ln2_b = (const float*)d_in[17];
    float* out = (float*)d_out;

    __half *hh, *qh, *kh, *vh, *vtp, *oh, *ffh;
    __half *cwqkv, *cwo, *cw1, *cw2;
    float  *x1, *bqkv;
    cudaGetSymbolAddress((void**)&hh,    g_hh);
    cudaGetSymbolAddress((void**)&qh,    g_qh);
    cudaGetSymbolAddress((void**)&kh,    g_kh);
    cudaGetSymbolAddress((void**)&vh,    g_vh);
    cudaGetSymbolAddress((void**)&vtp,   g_vt);
    cudaGetSymbolAddress((void**)&oh,    g_oh);
    cudaGetSymbolAddress((void**)&x1,    g_x1);
    cudaGetSymbolAddress((void**)&ffh,   g_ffh);
    cudaGetSymbolAddress((void**)&cwqkv, g_wqkv);
    cudaGetSymbolAddress((void**)&bqkv,  g_bqkv);
    cudaGetSymbolAddress((void**)&cwo,   g_wo);
    cudaGetSymbolAddress((void**)&cw1,   g_w1);
    cudaGetSymbolAddress((void**)&cw2,   g_w2);

    cudaFuncSetAttribute(fattn, cudaFuncAttributeMaxDynamicSharedMemorySize, FA_SMEM);
    cudaFuncSetAttribute(hgemm<1>, cudaFuncAttributeMaxDynamicSharedMemorySize, SMEM_H256);
    cudaFuncSetAttribute(hgemm<2>, cudaFuncAttributeMaxDynamicSharedMemorySize, SMEM_H256);
    cudaFuncSetAttribute(hgemm_qkv, cudaFuncAttributeMaxDynamicSharedMemorySize, SMEM_H256);

    // transpose + half-cvt the weights: [K,N] -> [N,K]; QKV fused buffer
    transpose_cvt<<<dim3(DMODEL/32, DMODEL/32), 256>>>(wq, cwqkv, DMODEL, DMODEL);
    transpose_cvt<<<dim3(HDIM/32,   DMODEL/32), 256>>>(wk, cwqkv + (size_t)DMODEL * DMODEL,
                                                       DMODEL, HDIM);
    transpose_cvt<<<dim3(HDIM/32,   DMODEL/32), 256>>>(wv, cwqkv + (size_t)(DMODEL + HDIM) * DMODEL,
                                                       DMODEL, HDIM);
    transpose_cvt<<<dim3(DMODEL/32, DMODEL/32), 256>>>(wo, cwo, DMODEL, DMODEL);
    transpose_cvt<<<dim3(FFDIM/32,  DMODEL/32), 256>>>(w1, cw1, DMODEL, FFDIM);
    transpose_cvt<<<dim3(DMODEL/32, FFDIM/32),  256>>>(w2, cw2, FFDIM, DMODEL);
    fill_bqkv<<<9, 256>>>(wq_b, wk_b, wv_b, bqkv);

    const float qscale = 0.08838834764831845f;  // 1/sqrt(128)

    // h = LN1(x)  (half)
    ln_kernel<<<MTOK, 256>>>(x, ln1_s, ln1_b, hh);
    // fused QKV projection
    hgemm_qkv<<<dim3(NQKV/GBN, MTOK/128), 256, SMEM_H256>>>(
        hh, cwqkv, bqkv, qh, kh, vh, DMODEL, qscale);
    // V transpose
    vtrans<<<dim3(HDIM/32, SEQ/32, 2), 256>>>(vh, vtp);
    // attention (half out)
    fattn<<<dim3(SEQ/128, 2*NHEAD), 256, FA_SMEM>>>(qh, kh, vtp, oh);
    // x1 = x + O @ wo + wo_b  (float out)
    hgemm<1><<<dim3(DMODEL/GBN, MTOK/128), 256, SMEM_H256>>>(
        oh, cwo, wo_b, x, x1, MTOK, DMODEL, DMODEL);
    // h = LN2(x1) (half)
    ln_kernel<<<MTOK, 256>>>(x1, ln2_s, ln2_b, hh);
    // ff = gelu(h @ w1 + w1_b)  (half out)
    hgemm<2><<<dim3(FFDIM/GBN, MTOK/128), 256, SMEM_H256>>>(
        hh, cw1, w1_b, nullptr, ffh, MTOK, FFDIM, DMODEL);
    // out = x1 + ff @ w2 + w2_b (float out)
    hgemm<1><<<dim3(DMODEL/GBN, MTOK/128), 256, SMEM_H256>>>(
        ffh, cw2, w2_b, x1, out, MTOK, DMODEL, FFDIM);
}

// round 10
// speedup vs baseline: 6.2728x; 1.0147x over previous
#include <cuda_runtime.h>
#include <cuda_fp16.h>
#include <math.h>
#include <stdint.h>

// Problem dims
#define MTOK   4096      // B*S
#define DMODEL 2048
#define NHEAD  16
#define HDIM   128
#define FFDIM  8192
#define SEQ    2048
#define NQKV   2304      // 2048 + 128 + 128

// ---------------- scratch (device globals: allocation-free) ----------------
__device__ __half g_hh [MTOK * DMODEL];          // LN output (half)
__device__ __half g_qh [MTOK * DMODEL];          // Q half (pre-scaled by 1/sqrt(hd)*log2e)
__device__ __half g_kh [MTOK * HDIM];            // K half
__device__ __half g_vh [MTOK * HDIM];            // V half
__device__ __half g_vt [2 * HDIM * SEQ];         // V transposed [B][HD][S]
__device__ __half g_oh [MTOK * DMODEL];          // attn O (half)
__device__ float  g_x1 [MTOK * DMODEL];          // x + attn_out
__device__ __half g_ffh[(size_t)MTOK * FFDIM];   // FF1 output (half)
// transposed ([K,N] -> [N,K]) half weights
__device__ __half g_wqkv[(size_t)NQKV * DMODEL]; // [Q;K;V] rows
__device__ float  g_bqkv[NQKV];
__device__ __half g_wo[DMODEL * DMODEL];
__device__ __half g_w1[(size_t)DMODEL * FFDIM];
__device__ __half g_w2[(size_t)FFDIM * DMODEL];

// ---------------- helpers ----------------
__device__ __forceinline__ float gelu_exact(float x) {
    return 0.5f * x * (1.0f + erff(x * 0.70710678118654752f));
}
__device__ __forceinline__ float ex2(float x) {
    float y; asm("ex2.approx.f32 %0, %1;" : "=f"(y) : "f"(x)); return y;
}
__device__ __forceinline__ void cp16(uint32_t saddr, const void* g) {
    asm volatile("cp.async.cg.shared.global [%0], [%1], 16;" :: "r"(saddr), "l"(g));
}
#define CP_COMMIT() asm volatile("cp.async.commit_group;\n")
#define CP_WAIT(n)  asm volatile("cp.async.wait_group %0;\n" :: "n"(n))

__device__ __forceinline__ void mma_f16(float* c, const uint32_t* a, const uint32_t* b) {
    asm volatile(
        "mma.sync.aligned.m16n8k16.row.col.f32.f16.f16.f32 "
        "{%0,%1,%2,%3}, {%4,%5,%6,%7}, {%8,%9}, {%0,%1,%2,%3};\n"
        : "+f"(c[0]), "+f"(c[1]), "+f"(c[2]), "+f"(c[3])
        : "r"(a[0]), "r"(a[1]), "r"(a[2]), "r"(a[3]), "r"(b[0]), "r"(b[1]));
}
#define LDSM4(r0, r1, r2, r3, addr) \
    asm volatile("ldmatrix.sync.aligned.m8n8.x4.shared.b16 {%0,%1,%2,%3}, [%4];" \
        : "=r"(r0), "=r"(r1), "=r"(r2), "=r"(r3) : "r"(addr))

__device__ __forceinline__ uint32_t packh2(float x, float y) {
    __half2 t = __floats2half2_rn(x, y);
    return *(uint32_t*)&t;
}

// ---------------- merged weight preprocessing ----------------
// Block ranges: wq [0,4096), wk [4096,4352), wv [4352,4608), wo [4608,8704),
//               w1 [8704,25088), w2 [25088,41472), bias [41472,41481)
__global__ __launch_bounds__(256) void prep_weights(
    const float* __restrict__ wq, const float* __restrict__ wk,
    const float* __restrict__ wv, const float* __restrict__ wo,
    const float* __restrict__ w1, const float* __restrict__ w2,
    const float* __restrict__ qb, const float* __restrict__ kb,
    const float* __restrict__ vb,
    __half* __restrict__ cwqkv, __half* __restrict__ cwo,
    __half* __restrict__ cw1, __half* __restrict__ cw2,
    float* __restrict__ bqkv)
{
    int bid = blockIdx.x;
    const float* in; __half* out; int K, N, tile;
    if (bid < 4096)       { in = wq; out = cwqkv;                          K = 2048; N = 2048; tile = bid; }
    else if (bid < 4352)  { in = wk; out = cwqkv + (size_t)2048 * 2048;    K = 2048; N = 128;  tile = bid - 4096; }
    else if (bid < 4608)  { in = wv; out = cwqkv + (size_t)2176 * 2048;    K = 2048; N = 128;  tile = bid - 4352; }
    else if (bid < 8704)  { in = wo; out = cwo;                            K = 2048; N = 2048; tile = bid - 4608; }
    else if (bid < 25088) { in = w1; out = cw1;                            K = 2048; N = 8192; tile = bid - 8704; }
    else if (bid < 41472) { in = w2; out = cw2;                            K = 8192; N = 2048; tile = bid - 25088; }
    else {
        int i = (bid - 41472) * 256 + threadIdx.x;
        if (i < DMODEL) bqkv[i] = qb[i];
        else if (i < DMODEL + HDIM) bqkv[i] = kb[i - DMODEL];
        else if (i < NQKV) bqkv[i] = vb[i - DMODEL - HDIM];
        return;
    }
    int nx = N >> 5;
    int bx = (tile % nx) * 32, by = (tile / nx) * 32;
    __shared__ float t[32][33];
    int tx = threadIdx.x & 31, ty = threadIdx.x >> 5;
    #pragma unroll
    for (int i = 0; i < 32; i += 8)
        t[ty + i][tx] = in[(size_t)(by + ty + i) * N + bx + tx];
    __syncthreads();
    #pragma unroll
    for (int i = 0; i < 32; i += 8)
        out[(size_t)(bx + ty + i) * K + by + tx] = __float2half(t[tx][ty + i]);
}

// ---------------- V transpose (half): [B*S, HD] -> [B][HD][S] ----------
__global__ __launch_bounds__(256) void vtrans(
    const __half* __restrict__ in, __half* __restrict__ out)
{
    __shared__ __half t[32][34];
    int b = blockIdx.z;
    int d0 = blockIdx.x * 32, s0 = blockIdx.y * 32;
    int tx = threadIdx.x & 31, ty = threadIdx.x >> 5;
    #pragma unroll
    for (int i = 0; i < 32; i += 8)
        t[ty + i][tx] = in[(size_t)(b * SEQ + s0 + ty + i) * HDIM + d0 + tx];
    __syncthreads();
    #pragma unroll
    for (int i = 0; i < 32; i += 8)
        out[(size_t)(b * HDIM + d0 + ty + i) * SEQ + s0 + tx] = t[tx][ty + i];
}

// ---------------- LayerNorm (half output) ----------------
__global__ __launch_bounds__(256) void ln_kernel(
    const float* __restrict__ x, const float* __restrict__ sc,
    const float* __restrict__ bi, __half* __restrict__ out)
{
    int row = blockIdx.x, tid = threadIdx.x;
    const float4* xr = (const float4*)(x + (size_t)row * DMODEL);
    float4 a = xr[tid];
    float4 b = xr[tid + 256];
    float s  = a.x + a.y + a.z + a.w + b.x + b.y + b.z + b.w;
    float ss = a.x*a.x + a.y*a.y + a.z*a.z + a.w*a.w
             + b.x*b.x + b.y*b.y + b.z*b.z + b.w*b.w;
    __shared__ float rs[8], rss[8];
    #pragma unroll
    for (int off = 16; off; off >>= 1) {
        s  += __shfl_xor_sync(0xffffffffu, s,  off);
        ss += __shfl_xor_sync(0xffffffffu, ss, off);
    }
    if ((tid & 31) == 0) { rs[tid >> 5] = s; rss[tid >> 5] = ss; }
    __syncthreads();
    float tot = 0.f, tot2 = 0.f;
    #pragma unroll
    for (int i = 0; i < 8; i++) { tot += rs[i]; tot2 += rss[i]; }
    float mean = tot * (1.0f / DMODEL);
    float var  = tot2 * (1.0f / DMODEL) - mean * mean;
    float rstd = rsqrtf(var + 1e-5f);

    const float4* s4 = (const float4*)sc;
    const float4* b4 = (const float4*)bi;
    float4 sc0 = s4[tid], bi0 = b4[tid], sc1 = s4[tid + 256], bi1 = b4[tid + 256];
    __half* orow = out + (size_t)row * DMODEL;
    union { uint2 u; __half2 h[2]; } p0, p1;
    p0.h[0] = __floats2half2_rn((a.x - mean) * rstd * sc0.x + bi0.x,
                                (a.y - mean) * rstd * sc0.y + bi0.y);
    p0.h[1] = __floats2half2_rn((a.z - mean) * rstd * sc0.z + bi0.z,
                                (a.w - mean) * rstd * sc0.w + bi0.w);
    p1.h[0] = __floats2half2_rn((b.x - mean) * rstd * sc1.x + bi1.x,
                                (b.y - mean) * rstd * sc1.y + bi1.y);
    p1.h[1] = __floats2half2_rn((b.z - mean) * rstd * sc1.z + bi1.z,
                                (b.w - mean) * rstd * sc1.w + bi1.w);
    *(uint2*)&orow[tid * 4]         = p0.u;
    *(uint2*)&orow[(tid + 256) * 4] = p1.u;
}

// ---------------- shared GEMM tiling constants ----------------
#define GBN  256
#define GKS  32
#define GST  4        // pipeline stages
#define GSA  40
#define GSB  40
#define GASZ (128 * GSA)
#define GBSZ (GBN * GSB)
#define GSTSZ (GASZ + GBSZ)
#define SMEM_H256 (GST * GSTSZ * 2)   // 122880 bytes

// 4-stage single-sync mainloop shared by both GEMM kernels -----------------
#define GEMM_MAINLOOP()                                                        \
    auto loadStage = [&](int slot, int k0) {                                   \
        uint32_t abase = sbase + (uint32_t)(slot * GSTSZ) * 2;                 \
        uint32_t bbase = abase + (uint32_t)GASZ * 2;                           \
        _Pragma("unroll")                                                      \
        for (int i = 0; i < 2; i++) {                                          \
            int ch = tid + i * 256;                                            \
            int m = ch >> 2, kc = (ch & 3) << 3;                               \
            cp16(abase + (uint32_t)(m * GSA + kc) * 2,                         \
                 Arow + (size_t)m * K + k0 + kc);                              \
        }                                                                      \
        _Pragma("unroll")                                                      \
        for (int i = 0; i < 4; i++) {                                          \
            int ch = tid + i * 256;                                            \
            int n = ch >> 2, kc = (ch & 3) << 3;                               \
            cp16(bbase + (uint32_t)(n * GSB + kc) * 2,                         \
                 Brow + (size_t)n * K + k0 + kc);                              \
        }                                                                      \
    };                                                                         \
    uint32_t aoff = ((uint32_t)((wm + (lane & 15)) * GSA + (lane >> 4) * 8)) * 2; \
    uint32_t boff = ((uint32_t)GASZ +                                          \
        (uint32_t)((wn + (lane >> 4) * 8 + (lane & 7)) * GSB +                 \
                   ((lane >> 3) & 1) * 8)) * 2;                                \
    loadStage(0, 0); CP_COMMIT();                                              \
    loadStage(1, GKS); CP_COMMIT();                                            \
    loadStage(2, 2 * GKS); CP_COMMIT();                                        \
    int T = K / GKS;                                                           \
    for (int t = 0; t < T; t++) {                                              \
        CP_WAIT(2);                                                            \
        __syncthreads();                                                       \
        if (t + 3 < T) { loadStage((t + 3) & 3, (t + 3) * GKS); }              \
        CP_COMMIT();                                                           \
        uint32_t aa = sbase + (uint32_t)((t & 3) * GSTSZ) * 2 + aoff;          \
        uint32_t bb = sbase + (uint32_t)((t & 3) * GSTSZ) * 2 + boff;          \
        _Pragma("unroll")                                                      \
        for (int kk = 0; kk < GKS; kk += 16) {                                 \
            uint32_t af[4][4];                                                 \
            _Pragma("unroll")                                                  \
            for (int mi = 0; mi < 4; mi++)                                     \
                LDSM4(af[mi][0], af[mi][1], af[mi][2], af[mi][3],              \
                      aa + (uint32_t)(kk * 2) + (uint32_t)(mi * 16 * GSA * 2));\
            uint32_t bf[8][2];                                                 \
            _Pragma("unroll")                                                  \
            for (int np = 0; np < 4; np++)                                     \
                LDSM4(bf[2*np][0], bf[2*np][1], bf[2*np+1][0], bf[2*np+1][1],  \
                      bb + (uint32_t)(kk * 2) + (uint32_t)(np * 16 * GSB * 2));\
            _Pragma("unroll")                                                  \
            for (int mi = 0; mi < 4; mi++)                                     \
                _Pragma("unroll")                                              \
                for (int ni = 0; ni < 8; ni++)                                 \
                    mma_f16(acc[mi][ni], af[mi], bf[ni]);                      \
        }                                                                      \
    }

// ---------------- FP16 GEMM (generic epilogues) ----------------
// EPI: 1 = +bias+residual (float out), 2 = +bias -> GELU (half out)
template<int EPI>
__global__ __launch_bounds__(256) void hgemm(
    const __half* __restrict__ A, const __half* __restrict__ Bt,
    const float* __restrict__ bias, const float* __restrict__ res,
    void* __restrict__ Cv, int M, int N, int K)
{
    extern __shared__ __half smem[];
    uint32_t sbase = (uint32_t)__cvta_generic_to_shared(smem);
    int tid = threadIdx.x, lane = tid & 31, w = tid >> 5;
    int wm = (w >> 2) * 64, wn = (w & 3) * 64;
    int r = lane >> 2, cl = lane & 3;
    int bm = blockIdx.y * 128, bn = blockIdx.x * GBN;

    float acc[4][8][4];
    #pragma unroll
    for (int mi = 0; mi < 4; mi++)
        #pragma unroll
        for (int ni = 0; ni < 8; ni++)
            #pragma unroll
            for (int j = 0; j < 4; j++) acc[mi][ni][j] = 0.f;

    const __half* Arow = A + (size_t)bm * K;
    const __half* Brow = Bt + (size_t)bn * K;
    GEMM_MAINLOOP();

    #pragma unroll
    for (int mi = 0; mi < 4; mi++) {
        #pragma unroll
        for (int ni = 0; ni < 8; ni++) {
            int row0 = bm + wm + mi * 16 + r;
            int col  = bn + wn + ni * 8 + cl * 2;
            float2 bv = *(const float2*)&bias[col];
            #pragma unroll
            for (int hh = 0; hh < 2; hh++) {
                int row = row0 + hh * 8;
                float v0 = acc[mi][ni][hh * 2 + 0] + bv.x;
                float v1 = acc[mi][ni][hh * 2 + 1] + bv.y;
                if (EPI == 1) {
                    float2 rv = *(const float2*)&res[(size_t)row * N + col];
                    float* Cf = (float*)Cv;
                    *(float2*)&Cf[(size_t)row * N + col] =
                        make_float2(v0 + rv.x, v1 + rv.y);
                } else {
                    __half* Ch = (__half*)Cv;
                    *(__half2*)&Ch[(size_t)row * N + col] =
                        __floats2half2_rn(gelu_exact(v0), gelu_exact(v1));
                }
            }
        }
    }
}

// ---------------- Fused QKV GEMM (N = 2304, routing epilogue) ----------------
__global__ __launch_bounds__(256) void hgemm_qkv(
    const __half* __restrict__ A, const __half* __restrict__ Bt,
    const float* __restrict__ bias,
    __half* __restrict__ qo, __half* __restrict__ ko, __half* __restrict__ vo,
    int K, float qscale)
{
    extern __shared__ __half smem[];
    uint32_t sbase = (uint32_t)__cvta_generic_to_shared(smem);
    int tid = threadIdx.x, lane = tid & 31, w = tid >> 5;
    int wm = (w >> 2) * 64, wn = (w & 3) * 64;
    int r = lane >> 2, cl = lane & 3;
    int bm = blockIdx.y * 128, bn = blockIdx.x * GBN;

    float acc[4][8][4];
    #pragma unroll
    for (int mi = 0; mi < 4; mi++)
        #pragma unroll
        for (int ni = 0; ni < 8; ni++)
            #pragma unroll
            for (int j = 0; j < 4; j++) acc[mi][ni][j] = 0.f;

    const __half* Arow = A + (size_t)bm * K;
    const __half* Brow = Bt + (size_t)bn * K;
    GEMM_MAINLOOP();

    #pragma unroll
    for (int mi = 0; mi < 4; mi++) {
        #pragma unroll
        for (int ni = 0; ni < 8; ni++) {
            int row0 = bm + wm + mi * 16 + r;
            int col  = bn + wn + ni * 8 + cl * 2;
            float2 bv = *(const float2*)&bias[col];
            #pragma unroll
            for (int hh = 0; hh < 2; hh++) {
                int row = row0 + hh * 8;
                float v0 = acc[mi][ni][hh * 2 + 0] + bv.x;
                float v1 = acc[mi][ni][hh * 2 + 1] + bv.y;
                if (col < DMODEL) {
                    *(__half2*)&qo[(size_t)row * DMODEL + col] =
                        __floats2half2_rn(v0 * qscale, v1 * qscale);
                } else if (col < DMODEL + HDIM) {
                    *(__half2*)&ko[(size_t)row * HDIM + (col - DMODEL)] =
                        __floats2half2_rn(v0, v1);
                } else {
                    *(__half2*)&vo[(size_t)row * HDIM + (col - DMODEL - HDIM)] =
                        __floats2half2_rn(v0, v1);
                }
            }
        }
    }
}

// ---------------- FP16 tensor-core flash attention (BQ=128, BK=128) ---------
// Q pre-scaled by log2(e)/sqrt(HD); softmax in base 2 (ex2.approx).
#define SQ  136
#define FA_SMEM (5 * 128 * SQ * 2)   // Q + 2xK + 2xV = 174080 bytes

__global__ __launch_bounds__(256) void fattn(
    const __half* __restrict__ q, const __half* __restrict__ k,
    const __half* __restrict__ vt, __half* __restrict__ o)
{
    extern __shared__ __half sm2[];
    uint32_t qb  = (uint32_t)__cvta_generic_to_shared(sm2);
    uint32_t kbb = qb + 128 * SQ * 2;        // [2][128][SQ]
    uint32_t vbb = kbb + 2 * 128 * SQ * 2;   // [2][128][SQ]

    int tid = threadIdx.x, lane = tid & 31, w = tid >> 5;
    int qt = (int)gridDim.x - 1 - (int)blockIdx.x;   // longest first
    int bh = blockIdx.y, b = bh >> 4, h = bh & 15;
    int qs0 = qt * 128;
    int r = lane >> 2, cl = lane & 3;
    int m0 = w * 16;

    const __half* qp = q + ((size_t)(b * SEQ + qs0) * NHEAD + h) * HDIM;
    #pragma unroll
    for (int i = 0; i < 8; i++) {
        int ch = tid + i * 256; int rr = ch >> 4, c = (ch & 15) * 8;
        cp16(qb + (uint32_t)(rr * SQ + c) * 2, qp + (size_t)rr * (NHEAD * HDIM) + c);
    }

    auto loadKV = [&](int st, int kt) {
        int ks0 = kt * 128;
        const __half* kp = k + ((size_t)b * SEQ + ks0) * HDIM;
        uint32_t kbs = kbb + (uint32_t)st * 128 * SQ * 2;
        #pragma unroll
        for (int i = 0; i < 8; i++) {
            int ch = tid + i * 256; int rr = ch >> 4, c = (ch & 15) * 8;
            cp16(kbs + (uint32_t)(rr * SQ + c) * 2, kp + (size_t)rr * HDIM + c);
        }
        const __half* vp = vt + (size_t)b * HDIM * SEQ + ks0;
        uint32_t vbs = vbb + (uint32_t)st * 128 * SQ * 2;
        #pragma unroll
        for (int i = 0; i < 8; i++) {
            int ch = tid + i * 256; int rr = ch >> 4, c = (ch & 15) * 8;
            cp16(vbs + (uint32_t)(rr * SQ + c) * 2, vp + (size_t)rr * SEQ + c);
        }
    };

    loadKV(0, 0);
    CP_COMMIT();

    uint32_t qaddr = qb + (uint32_t)((m0 + (lane & 15)) * SQ + (lane >> 4) * 8) * 2;
    uint32_t koff  = (uint32_t)(((lane >> 4) * 8 + (lane & 7)) * SQ +
                                ((lane >> 3) & 1) * 8) * 2;
    uint32_t voff  = koff;

    float m_0 = -1e30f, m_1 = -1e30f, l_0 = 0.f, l_1 = 0.f;
    float oacc[16][4];
    #pragma unroll
    for (int di = 0; di < 16; di++)
        #pragma unroll
        for (int j = 0; j < 4; j++) oacc[di][j] = 0.f;

    int nkt = qt + 1;
    for (int kt = 0; kt < nkt; kt++) {
        CP_WAIT(0);
        __syncthreads();
        if (kt + 1 < nkt) { loadKV((kt + 1) & 1, kt + 1); CP_COMMIT(); }
        uint32_t ka = kbb + (uint32_t)((kt & 1) * 128 * SQ) * 2 + koff;
        uint32_t va = vbb + (uint32_t)((kt & 1) * 128 * SQ) * 2 + voff;

        // S = Q K^T  (16 x 128 per warp)
        float sacc[16][4];
        #pragma unroll
        for (int ni = 0; ni < 16; ni++)
            #pragma unroll
            for (int j = 0; j < 4; j++) sacc[ni][j] = 0.f;

        #pragma unroll
        for (int kk = 0; kk < 128; kk += 16) {
            uint32_t af[4];
            LDSM4(af[0], af[1], af[2], af[3], qaddr + (uint32_t)(kk * 2));
            uint32_t bf[16][2];
            #pragma unroll
            for (int np = 0; np < 8; np++)
                LDSM4(bf[2*np][0], bf[2*np][1], bf[2*np+1][0], bf[2*np+1][1],
                      ka + (uint32_t)(kk * 2) + (uint32_t)(np * 16 * SQ * 2));
            #pragma unroll
            for (int ni = 0; ni < 16; ni++)
                mma_f16(sacc[ni], af, bf[ni]);
        }

        // causal mask: only the diagonal tile needs it
        if (kt == qt) {
            int ks0 = kt * 128;
            int row0 = qs0 + m0 + r, row1 = row0 + 8;
            #pragma unroll
            for (int ni = 0; ni < 16; ni++) {
                int c0 = ks0 + ni * 8 + cl * 2, c1 = c0 + 1;
                if (c0 > row0) sacc[ni][0] = -1e30f;
                if (c1 > row0) sacc[ni][1] = -1e30f;
                if (c0 > row1) sacc[ni][2] = -1e30f;
                if (c1 > row1) sacc[ni][3] = -1e30f;
            }
        }

        // online softmax (base 2)
        float mx0 = -1e30f, mx1 = -1e30f;
        #pragma unroll
        for (int ni = 0; ni < 16; ni++) {
            mx0 = fmaxf(mx0, fmaxf(sacc[ni][0], sacc[ni][1]));
            mx1 = fmaxf(mx1, fmaxf(sacc[ni][2], sacc[ni][3]));
        }
        mx0 = fmaxf(mx0, __shfl_xor_sync(0xffffffffu, mx0, 1));
        mx0 = fmaxf(mx0, __shfl_xor_sync(0xffffffffu, mx0, 2));
        mx1 = fmaxf(mx1, __shfl_xor_sync(0xffffffffu, mx1, 1));
        mx1 = fmaxf(mx1, __shfl_xor_sync(0xffffffffu, mx1, 2));
        float mn0 = fmaxf(m_0, mx0), mn1 = fmaxf(m_1, mx1);
        float a0 = ex2(m_0 - mn0), a1 = ex2(m_1 - mn1);
        float s0 = 0.f, s1 = 0.f;
        #pragma unroll
        for (int ni = 0; ni < 16; ni++) {
            sacc[ni][0] = ex2(sacc[ni][0] - mn0);
            sacc[ni][1] = ex2(sacc[ni][1] - mn0);
            sacc[ni][2] = ex2(sacc[ni][2] - mn1);
            sacc[ni][3] = ex2(sacc[ni][3] - mn1);
            s0 += sacc[ni][0] + sacc[ni][1];
            s1 += sacc[ni][2] + sacc[ni][3];
        }
        s0 += __shfl_xor_sync(0xffffffffu, s0, 1);
        s0 += __shfl_xor_sync(0xffffffffu, s0, 2);
        s1 += __shfl_xor_sync(0xffffffffu, s1, 1);
        s1 += __shfl_xor_sync(0xffffffffu, s1, 2);
        l_0 = l_0 * a0 + s0; l_1 = l_1 * a1 + s1;
        m_0 = mn0; m_1 = mn1;
        #pragma unroll
        for (int di = 0; di < 16; di++) {
            oacc[di][0] *= a0; oacc[di][1] *= a0;
            oacc[di][2] *= a1; oacc[di][3] *= a1;
        }

        // P fragments (registers -> A-frag)
        uint32_t pa[8][4];
        #pragma unroll
        for (int j = 0; j < 8; j++) {
            pa[j][0] = packh2(sacc[2*j  ][0], sacc[2*j  ][1]);
            pa[j][1] = packh2(sacc[2*j  ][2], sacc[2*j  ][3]);
            pa[j][2] = packh2(sacc[2*j+1][0], sacc[2*j+1][1]);
            pa[j][3] = packh2(sacc[2*j+1][2], sacc[2*j+1][3]);
        }

        // O += P V
        #pragma unroll
        for (int j = 0; j < 8; j++) {
            #pragma unroll
            for (int dp = 0; dp < 8; dp++) {
                uint32_t bf[4];
                LDSM4(bf[0], bf[1], bf[2], bf[3],
                      va + (uint32_t)(j * 16 * 2) + (uint32_t)(dp * 16 * SQ * 2));
                mma_f16(oacc[2*dp    ], pa[j], bf    );
                mma_f16(oacc[2*dp + 1], pa[j], bf + 2);
            }
        }
    }

    // epilogue
    float i0 = 1.f / l_0, i1 = 1.f / l_1;
    __half* op = o + ((size_t)(b * SEQ + qs0 + m0) * NHEAD + h) * HDIM;
    #pragma unroll
    for (int di = 0; di < 16; di++) {
        int c = di * 8 + cl * 2;
        *(__half2*)&op[(size_t)r * (NHEAD * HDIM) + c] =
            __floats2half2_rn(oacc[di][0] * i0, oacc[di][1] * i0);
        *(__half2*)&op[(size_t)(r + 8) * (NHEAD * HDIM) + c] =
            __floats2half2_rn(oacc[di][2] * i1, oacc[di][3] * i1);
    }
}

// ---------------- launch ----------------
extern "C" void kernel_launch(void* const* d_in, const int* in_sizes, int n_in,
                              void* d_out, int out_size)
{
    const float* x     = (const float*)d_in[0];
    const float* wq    = (const float*)d_in[2];
    const float* wq_b  = (const float*)d_in[3];
    const float* wk    = (const float*)d_in[4];
    const float* wk_b  = (const float*)d_in[5];
    const float* wv    = (const float*)d_in[6];
    const float* wv_b  = (const float*)d_in[7];
    const float* wo    = (const float*)d_in[8];
    const float* wo_b  = (const float*)d_in[9];
    const float* w1    = (const float*)d_in[10];
    const float* w1_b  = (const float*)d_in[11];
    const float* w2    = (const float*)d_in[12];
    const float* w2_b  = (const float*)d_in[13];
    const float* ln1_s = (const float*)d_in[14];
    const float* ln1_b = (const float*)d_in[15];
    const float* ln2_s = (const float*)d_in[16];
    const float* ln2_b = (const float*)d_in[17];
    float* out = (float*)d_out;

    __half *hh, *qh, *kh, *vh, *vtp, *oh, *ffh;
    __half *cwqkv, *cwo, *cw1, *cw2;
    float  *x1, *bqkv;
    cudaGetSymbolAddress((void**)&hh,    g_hh);
    cudaGetSymbolAddress((void**)&qh,    g_qh);
    cudaGetSymbolAddress((void**)&kh,    g_kh);
    cudaGetSymbolAddress((void**)&vh,    g_vh);
    cudaGetSymbolAddress((void**)&vtp,   g_vt);
    cudaGetSymbolAddress((void**)&oh,    g_oh);
    cudaGetSymbolAddress((void**)&x1,    g_x1);
    cudaGetSymbolAddress((void**)&ffh,   g_ffh);
    cudaGetSymbolAddress((void**)&cwqkv, g_wqkv);
    cudaGetSymbolAddress((void**)&bqkv,  g_bqkv);
    cudaGetSymbolAddress((void**)&cwo,   g_wo);
    cudaGetSymbolAddress((void**)&cw1,   g_w1);
    cudaGetSymbolAddress((void**)&cw2,   g_w2);

    cudaFuncSetAttribute(fattn, cudaFuncAttributeMaxDynamicSharedMemorySize, FA_SMEM);
    cudaFuncSetAttribute(hgemm<1>, cudaFuncAttributeMaxDynamicSharedMemorySize, SMEM_H256);
    cudaFuncSetAttribute(hgemm<2>, cudaFuncAttributeMaxDynamicSharedMemorySize, SMEM_H256);
    cudaFuncSetAttribute(hgemm_qkv, cudaFuncAttributeMaxDynamicSharedMemorySize, SMEM_H256);

    // Q pre-scale folds softmax scale AND log2(e) for base-2 softmax
    const float qscale = 0.08838834764831845f * 1.44269504088896340f;

    // 1: all weight preprocessing in one launch
    prep_weights<<<41481, 256>>>(wq, wk, wv, wo, w1, w2, wq_b, wk_b, wv_b,
                                 cwqkv, cwo, cw1, cw2, bqkv);
    // 2: h = LN1(x)  (half)
    ln_kernel<<<MTOK, 256>>>(x, ln1_s, ln1_b, hh);
    // 3: fused QKV projection
    hgemm_qkv<<<dim3(NQKV/GBN, MTOK/128), 256, SMEM_H256>>>(
        hh, cwqkv, bqkv, qh, kh, vh, DMODEL, qscale);
    // 4: V transpose
    vtrans<<<dim3(HDIM/32, SEQ/32, 2), 256>>>(vh, vtp);
    // 5: attention (half out)
    fattn<<<dim3(SEQ/128, 2*NHEAD), 256, FA_SMEM>>>(qh, kh, vtp, oh);
    // 6: x1 = x + O @ wo + wo_b  (float out)   <-- ncu -s 5 -c 1 captures this
    hgemm<1><<<dim3(DMODEL/GBN, MTOK/128), 256, SMEM_H256>>>(
        oh, cwo, wo_b, x, x1, MTOK, DMODEL, DMODEL);
    // 7: h = LN2(x1) (half)
    ln_kernel<<<MTOK, 256>>>(x1, ln2_s, ln2_b, hh);
    // 8: ff = gelu(h @ w1 + w1_b)  (half out)
    hgemm<2><<<dim3(FFDIM/GBN, MTOK/128), 256, SMEM_H256>>>(
        hh, cw1, w1_b, nullptr, ffh, MTOK, FFDIM, DMODEL);
    // 9: out = x1 + ff @ w2 + w2_b (float out)
    hgemm<1><<<dim3(DMODEL/GBN, MTOK/128), 256, SMEM_H256>>>(
        ffh, cw2, w2_b, x1, out, MTOK, DMODEL, FFDIM);
}